// round 14
// baseline (speedup 1.0000x reference)
#include <cuda_runtime.h>

// ---------------- problem constants ----------------
#define B_      16
#define N_      64
#define P_      6
#define D_      8
#define E_      128
#define H_      8
#define HD_     16
#define S_      512            // N*D tokens per batch
#define TOK_    (B_*S_)        // 8192
#define KVN_    (B_*2*S_)      // 16384
#define NPROTO_ 256            // D * 32 prototype rows
#define I_      64
#define O_      128
#define KOUT_   (S_*E_)        // 65536
#define KCHUNKS_ 256
#define KCSZ_   (KOUT_/KCHUNKS_) // 256

// ---------------- device scratch (no allocations allowed) ----------------
__device__ float g_IE  [TOK_*E_];
__device__ float g_PE  [TOK_*E_];
__device__ float g_Q   [TOK_*E_];     // tf32 bit patterns (attention-only)
__device__ float g_KVO [KVN_*2*E_];   // tf32 bit patterns; cols 0..127 K, 128..255 V
__device__ float g_AT  [TOK_*E_];
__device__ float g_AP  [TOK_*E_];
__device__ float g_H1  [TOK_*E_];
__device__ float g_F1  [TOK_*I_];
__device__ float g_F2  [TOK_*E_];
__device__ float g_Z   [TOK_*E_];
__device__ float g_PART[KCHUNKS_*B_*O_];
__device__ float g_QN  [TOK_*H_];     // per (qrow, head) L2 norm
__device__ float g_KMAX[B_*H_];       // per (b, head) max key norm^2 (bits, atomicMax)
__device__ float g_OP  [2][TOK_*E_];  // split-key partial unnormalized outputs
__device__ float g_LP  [2][TOK_*H_];  // split-key partial softmax sums

__device__ __forceinline__ float* bufptr(int id){
    switch(id){
        case 0: return g_IE;
        case 2: return g_Q;
        case 3: return g_KVO;
        case 4: return g_AT;
        case 5: return g_AP;
        case 6: return g_H1;
        case 7: return g_F1;
        case 8: return g_F2;
        default: return g_Z;
    }
}

// ---------------- tf32 helpers ----------------
__device__ __forceinline__ unsigned f2tf(float f){
    unsigned r; asm("cvt.rna.tf32.f32 %0, %1;" : "=r"(r) : "f"(f)); return r;
}
__device__ __forceinline__ void mma_tf32(float c[4], const unsigned a[4], const unsigned b[2]){
    asm volatile("mma.sync.aligned.m16n8k8.row.col.f32.tf32.tf32.f32 "
        "{%0,%1,%2,%3}, {%4,%5,%6,%7}, {%8,%9}, {%0,%1,%2,%3};"
        : "+f"(c[0]), "+f"(c[1]), "+f"(c[2]), "+f"(c[3])
        : "r"(a[0]), "r"(a[1]), "r"(a[2]), "r"(a[3]), "r"(b[0]), "r"(b[1]));
}

// ---------------- rowprep: proto inorm (in-block) + x inorm + argmax + embeds ----
__global__ void k_rowprep(const float* __restrict__ x, const float* __restrict__ proto,
                          const float* __restrict__ Wemb, const float* __restrict__ bemb,
                          const float* __restrict__ Wpro, const float* __restrict__ bpro){
    __shared__ float sPN  [NPROTO_*P_];
    __shared__ float sPNL2[NPROTO_*P_];
    __shared__ float sWe[E_*P_];
    __shared__ float sWp[E_*P_];
    __shared__ float sbe[E_];
    __shared__ float sbp[E_];
    int tid = threadIdx.x;
    if (blockIdx.x == 0 && tid < B_*H_) g_KMAX[tid] = 0.f;
    {
        float v[P_]; float s = 0.f;
        #pragma unroll
        for (int p = 0; p < P_; p++){ v[p] = proto[tid*P_ + p]; s += v[p]; }
        float m = s * (1.f/P_);
        float var = 0.f;
        #pragma unroll
        for (int p = 0; p < P_; p++){ float dd = v[p]-m; var += dd*dd; }
        var *= (1.f/P_);
        float rs = rsqrtf(var + 1e-5f);
        float nrm = 0.f;
        #pragma unroll
        for (int p = 0; p < P_; p++){ v[p] = (v[p]-m)*rs; nrm += v[p]*v[p]; sPN[tid*P_+p] = v[p]; }
        float inv = 1.f / fmaxf(sqrtf(nrm), 1e-12f);
        #pragma unroll
        for (int p = 0; p < P_; p++) sPNL2[tid*P_+p] = v[p]*inv;
    }
    for (int i = tid; i < E_*P_; i += 256){ sWe[i] = Wemb[i]; sWp[i] = Wpro[i]; }
    if (tid < E_){ sbe[tid] = bemb[tid]; sbp[tid] = bpro[tid]; }
    __syncthreads();

    int warp = tid >> 5, lane = tid & 31;
    int r = blockIdx.x*8 + warp;
    int b = r >> 9; int n = (r >> 3) & 63; int d = r & 7;
    const float* xp = x + ((b*64 + n)*6)*8 + d;

    float v[6]; float s = 0.f;
    #pragma unroll
    for (int p = 0; p < 6; p++){ v[p] = xp[p*8]; s += v[p]; }
    float mean = s * (1.f/6.f);
    float var = 0.f;
    #pragma unroll
    for (int p = 0; p < 6; p++){ float dd = v[p]-mean; var += dd*dd; }
    var *= (1.f/6.f);
    float rs = rsqrtf(var + 1e-5f);
    float xn[6];
    #pragma unroll
    for (int p = 0; p < 6; p++) xn[p] = (v[p]-mean)*rs;

    float best = -1e30f; int bi = 0;
    #pragma unroll
    for (int i = 0; i < 8; i++){
        int pidx = i*32 + lane;
        const float* pr = &sPNL2[pidx*6];
        float sim = xn[0]*pr[0] + xn[1]*pr[1] + xn[2]*pr[2]
                  + xn[3]*pr[3] + xn[4]*pr[4] + xn[5]*pr[5];
        if (sim > best){ best = sim; bi = pidx; }
    }
    #pragma unroll
    for (int off = 16; off; off >>= 1){
        float ov = __shfl_xor_sync(0xffffffffu, best, off);
        int   oi = __shfl_xor_sync(0xffffffffu, bi,   off);
        if (ov > best || (ov == best && oi < bi)){ best = ov; bi = oi; }
    }

    float sel[6];
    #pragma unroll
    for (int p = 0; p < 6; p++) sel[p] = sPN[bi*6 + p];

    #pragma unroll
    for (int e4 = 0; e4 < 4; e4++){
        int e = e4*32 + lane;
        const float* we = &sWe[e*6];
        const float* wp = &sWp[e*6];
        float a1 = sbe[e], a2 = sbp[e];
        #pragma unroll
        for (int p = 0; p < 6; p++){ a1 += xn[p]*we[p]; a2 += sel[p]*wp[p]; }
        g_IE[r*E_ + e] = a1;
        g_PE[r*E_ + e] = a2;
    }
}

// ---------------- tf32 tensor-core GEMM, fragment-major smem ------------------
// EPI: 0 = plain fp32 store; 1 = tf32-bit store + q-norm; 2 = tf32-bit store + kmax.
template<int RELU, int CONCAT, int KK, int EPI>
__global__ void __launch_bounds__(256) k_mmagemm(int aId, const float* __restrict__ W,
                        const float* __restrict__ bias, int cId, int Nn){
    __shared__ __align__(16) unsigned sA[32*132];
    __shared__ __align__(16) unsigned sW[32*66];
    float* C = bufptr(cId);
    int t = threadIdx.x;
    int m0 = blockIdx.x * 128, n0 = blockIdx.y * 64;
    const float* Abase;
    if (CONCAT){
        int bb = m0 >> 10, j = m0 & 1023;
        Abase = ((j < 512) ? g_IE : g_PE) + (size_t)(bb*512 + (j & 511)) * KK;
    } else {
        Abase = bufptr(aId) + (size_t)m0 * KK;
    }
    int lane = t & 31, warp = t >> 5;
    int wm = warp >> 1, wn = warp & 1;
    int lq = lane >> 2, lc = lane & 3;
    int arow = t >> 3, ac4 = (t & 7)*4;
    int ksld = ac4 >> 3;
    int aslot = 2*((ac4 >> 2) & 1);
    int bslot = (ac4 >> 2) & 1;

    float c[2][4][4];
    #pragma unroll
    for (int mt = 0; mt < 2; mt++)
        #pragma unroll
        for (int nt = 0; nt < 4; nt++)
            c[mt][nt][0]=c[mt][nt][1]=c[mt][nt][2]=c[mt][nt][3]=0.f;

    float4 pa[4], pw[2];
    #pragma unroll
    for (int i = 0; i < 4; i++)
        pa[i] = *(const float4*)&Abase[(size_t)(arow + i*32)*KK + ac4];
    #pragma unroll
    for (int i = 0; i < 2; i++)
        pw[i] = *(const float4*)&W[(size_t)(n0 + arow + i*32)*KK + ac4];

    for (int k0 = 0; k0 < KK; k0 += 32){
        #pragma unroll
        for (int i = 0; i < 4; i++){
            int row = arow + i*32;
            int fa = (row >> 4)*4 + ksld;
            unsigned* d = &sA[fa*132 + (row & 7)*16 + ((row >> 3) & 1) + aslot];
            d[0]=f2tf(pa[i].x); d[4]=f2tf(pa[i].y); d[8]=f2tf(pa[i].z); d[12]=f2tf(pa[i].w);
        }
        #pragma unroll
        for (int i = 0; i < 2; i++){
            int row = arow + i*32;
            int fb = (row >> 3)*4 + ksld;
            unsigned* d = &sW[fb*66 + (row & 7)*8 + bslot];
            d[0]=f2tf(pw[i].x); d[2]=f2tf(pw[i].y); d[4]=f2tf(pw[i].z); d[6]=f2tf(pw[i].w);
        }
        __syncthreads();
        if (k0 + 32 < KK){
            #pragma unroll
            for (int i = 0; i < 4; i++)
                pa[i] = *(const float4*)&Abase[(size_t)(arow + i*32)*KK + k0 + 32 + ac4];
            #pragma unroll
            for (int i = 0; i < 2; i++)
                pw[i] = *(const float4*)&W[(size_t)(n0 + arow + i*32)*KK + k0 + 32 + ac4];
        }
        #pragma unroll
        for (int ks = 0; ks < 4; ks++){
            unsigned a[2][4], bf[4][2];
            #pragma unroll
            for (int mt = 0; mt < 2; mt++)
                *(uint4*)a[mt] = *(const uint4*)&sA[((2*wm + mt)*4 + ks)*132 + lane*4];
            #pragma unroll
            for (int nt = 0; nt < 4; nt++)
                *(uint2*)bf[nt] = *(const uint2*)&sW[((4*wn + nt)*4 + ks)*66 + lane*2];
            #pragma unroll
            for (int mt = 0; mt < 2; mt++)
                #pragma unroll
                for (int nt = 0; nt < 4; nt++)
                    mma_tf32(c[mt][nt], a[mt], bf[nt]);
        }
        __syncthreads();
    }
    #pragma unroll
    for (int nt = 0; nt < 4; nt++){
        int col = n0 + wn*32 + nt*8 + 2*lc;
        float b0 = bias[col], b1 = bias[col+1];
        #pragma unroll
        for (int mt = 0; mt < 2; mt++){
            int row = m0 + wm*32 + mt*16 + lq;
            float v0 = c[mt][nt][0] + b0, v1 = c[mt][nt][1] + b1;
            float v2 = c[mt][nt][2] + b0, v3 = c[mt][nt][3] + b1;
            if (RELU){
                v0 = fmaxf(v0,0.f); v1 = fmaxf(v1,0.f);
                v2 = fmaxf(v2,0.f); v3 = fmaxf(v3,0.f);
            }
            if (EPI == 0){
                *(float2*)&C[(size_t)row*Nn + col]     = make_float2(v0, v1);
                *(float2*)&C[(size_t)(row+8)*Nn + col] = make_float2(v2, v3);
            } else {
                *(float2*)&C[(size_t)row*Nn + col] = make_float2(
                    __uint_as_float(f2tf(v0)), __uint_as_float(f2tf(v1)));
                *(float2*)&C[(size_t)(row+8)*Nn + col] = make_float2(
                    __uint_as_float(f2tf(v2)), __uint_as_float(f2tf(v3)));
            }
            c[mt][nt][0]=v0; c[mt][nt][1]=v1; c[mt][nt][2]=v2; c[mt][nt][3]=v3;
        }
    }
    if (EPI == 1){
        #pragma unroll
        for (int p = 0; p < 2; p++){
            int head = (n0 >> 4) + wn*2 + p;
            #pragma unroll
            for (int mt = 0; mt < 2; mt++){
                float s0 = 0.f, s1 = 0.f;
                #pragma unroll
                for (int q = 0; q < 2; q++){
                    int nt = 2*p + q;
                    s0 += c[mt][nt][0]*c[mt][nt][0] + c[mt][nt][1]*c[mt][nt][1];
                    s1 += c[mt][nt][2]*c[mt][nt][2] + c[mt][nt][3]*c[mt][nt][3];
                }
                s0 += __shfl_xor_sync(0xffffffffu, s0, 1);
                s0 += __shfl_xor_sync(0xffffffffu, s0, 2);
                s1 += __shfl_xor_sync(0xffffffffu, s1, 1);
                s1 += __shfl_xor_sync(0xffffffffu, s1, 2);
                if (lc == 0){
                    int row = m0 + wm*32 + mt*16 + lq;
                    g_QN[row*8 + head]     = sqrtf(s0);
                    g_QN[(row+8)*8 + head] = sqrtf(s1);
                }
            }
        }
    }
    if (EPI == 2 && n0 < 128){
        int bb = m0 >> 10;
        #pragma unroll
        for (int p = 0; p < 2; p++){
            int head = (n0 >> 4) + wn*2 + p;
            float mx = 0.f;
            #pragma unroll
            for (int mt = 0; mt < 2; mt++){
                float s0 = 0.f, s1 = 0.f;
                #pragma unroll
                for (int q = 0; q < 2; q++){
                    int nt = 2*p + q;
                    s0 += c[mt][nt][0]*c[mt][nt][0] + c[mt][nt][1]*c[mt][nt][1];
                    s1 += c[mt][nt][2]*c[mt][nt][2] + c[mt][nt][3]*c[mt][nt][3];
                }
                s0 += __shfl_xor_sync(0xffffffffu, s0, 1);
                s0 += __shfl_xor_sync(0xffffffffu, s0, 2);
                s1 += __shfl_xor_sync(0xffffffffu, s1, 1);
                s1 += __shfl_xor_sync(0xffffffffu, s1, 2);
                mx = fmaxf(mx, fmaxf(s0, s1));
            }
            #pragma unroll
            for (int off = 16; off; off >>= 1)
                mx = fmaxf(mx, __shfl_xor_sync(0xffffffffu, mx, off));
            if (lane == 0)
                atomicMax((unsigned*)&g_KMAX[bb*8 + head], __float_as_uint(mx));
        }
    }
}

// ---------------- attention: split-key, 8 warps/block, 32 q rows/warp ---------
// grid = B*H*2*2: (bh, q-half, key-half). Writes unnormalized partials.
__global__ void __launch_bounds__(256) k_attn(){
    __shared__ unsigned sK[32*20];
    __shared__ unsigned sV[32*24];
    int blk = blockIdx.x;                 // 0..511
    int bh = blk >> 2, qh = (blk >> 1) & 1, kh = blk & 1;
    int b = bh >> 3, h = bh & 7;
    int t = threadIdx.x;
    int lane = t & 31, warp = t >> 5;
    int lq = lane >> 2, lc = lane & 3;
    int qrow0 = b*512 + qh*256 + warp*32;
    int hoff = h*16;
    const unsigned* Qb  = (const unsigned*)(g_Q  + (size_t)qrow0*E_ + hoff);
    const unsigned* KVb = (const unsigned*)(g_KVO + (size_t)(b*1024)*256);

    unsigned qa[2][2][4];
    #pragma unroll
    for (int mt = 0; mt < 2; mt++)
        #pragma unroll
        for (int ks = 0; ks < 2; ks++){
            const unsigned* qp = Qb + (size_t)(mt*16)*E_ + ks*8;
            qa[mt][ks][0] = qp[(size_t)lq*E_     + lc];
            qa[mt][ks][1] = qp[(size_t)(lq+8)*E_ + lc];
            qa[mt][ks][2] = qp[(size_t)lq*E_     + lc+4];
            qa[mt][ks][3] = qp[(size_t)(lq+8)*E_ + lc+4];
        }

    float kmax = sqrtf(g_KMAX[bh]);
    float mb[2][2];
    #pragma unroll
    for (int mt = 0; mt < 2; mt++){
        mb[mt][0] = g_QN[(qrow0 + mt*16 + lq  )*8 + h] * kmax * 0.25f;
        mb[mt][1] = g_QN[(qrow0 + mt*16 + lq+8)*8 + h] * kmax * 0.25f;
    }

    float o[2][2][4];
    #pragma unroll
    for (int mt = 0; mt < 2; mt++)
        #pragma unroll
        for (int d = 0; d < 2; d++)
            o[mt][d][0]=o[mt][d][1]=o[mt][d][2]=o[mt][d][3]=0.f;
    float lsum[2][2] = {};

    int s1 = (lane & 28) | (lc >> 1);
    int s2 = s1 + 2;
    bool odd = lc & 1;

    int sj = t >> 3, sf = t & 7;
    int scol = (sf & 3)*4;
    int key_begin = kh*512, key_end = key_begin + 512;

    #pragma unroll 1
    for (int key0 = key_begin; key0 < key_end; key0 += 32){
        {
            const unsigned* src = KVb + (size_t)(key0 + sj)*256 +
                               ((sf < 4) ? (hoff + scol) : (128 + hoff + scol));
            uint4 v = *(const uint4*)src;
            unsigned* dst = (sf < 4) ? &sK[sj*20 + scol] : &sV[sj*24 + scol];
            *(uint4*)dst = v;
        }
        __syncthreads();

        #pragma unroll
        for (int sub = 0; sub < 2; sub++){
            int r16 = sub*16;
            unsigned kb[2][2][2];
            #pragma unroll
            for (int nt = 0; nt < 2; nt++)
                #pragma unroll
                for (int ks = 0; ks < 2; ks++){
                    const unsigned* kp = &sK[(r16 + nt*8 + lq)*20 + ks*8 + lc];
                    kb[nt][ks][0] = kp[0];
                    kb[nt][ks][1] = kp[4];
                }
            float s[2][2][4];
            #pragma unroll
            for (int mt = 0; mt < 2; mt++)
                #pragma unroll
                for (int nt = 0; nt < 2; nt++){
                    s[mt][nt][0]=s[mt][nt][1]=s[mt][nt][2]=s[mt][nt][3]=0.f;
                    mma_tf32(s[mt][nt], qa[mt][0], kb[nt][0]);
                    mma_tf32(s[mt][nt], qa[mt][1], kb[nt][1]);
                }
            #pragma unroll
            for (int mt = 0; mt < 2; mt++)
                #pragma unroll
                for (int nt = 0; nt < 2; nt++){
                    float q0 = __expf(s[mt][nt][0]*0.25f - mb[mt][0]);
                    float q1 = __expf(s[mt][nt][1]*0.25f - mb[mt][0]);
                    float q2 = __expf(s[mt][nt][2]*0.25f - mb[mt][1]);
                    float q3 = __expf(s[mt][nt][3]*0.25f - mb[mt][1]);
                    s[mt][nt][0]=q0; s[mt][nt][1]=q1; s[mt][nt][2]=q2; s[mt][nt][3]=q3;
                    lsum[mt][0] += q0 + q1;
                    lsum[mt][1] += q2 + q3;
                }
            unsigned vb[2][2][2];
            #pragma unroll
            for (int kt = 0; kt < 2; kt++)
                #pragma unroll
                for (int d = 0; d < 2; d++){
                    const unsigned* vp = &sV[(r16 + kt*8 + lc)*24 + d*8 + lq];
                    vb[kt][d][0] = vp[0];
                    vb[kt][d][1] = vp[4*24];
                }
            #pragma unroll
            for (int mt = 0; mt < 2; mt++)
                #pragma unroll
                for (int kt = 0; kt < 2; kt++){
                    unsigned a[4];
                    float w0 = __shfl_sync(0xffffffffu, s[mt][kt][0], s1);
                    float w1 = __shfl_sync(0xffffffffu, s[mt][kt][1], s1);
                    a[0] = __float_as_uint(odd ? w1 : w0);
                    float w2 = __shfl_sync(0xffffffffu, s[mt][kt][2], s1);
                    float w3 = __shfl_sync(0xffffffffu, s[mt][kt][3], s1);
                    a[1] = __float_as_uint(odd ? w3 : w2);
                    w0 = __shfl_sync(0xffffffffu, s[mt][kt][0], s2);
                    w1 = __shfl_sync(0xffffffffu, s[mt][kt][1], s2);
                    a[2] = __float_as_uint(odd ? w1 : w0);
                    w2 = __shfl_sync(0xffffffffu, s[mt][kt][2], s2);
                    w3 = __shfl_sync(0xffffffffu, s[mt][kt][3], s2);
                    a[3] = __float_as_uint(odd ? w3 : w2);
                    mma_tf32(o[mt][0], a, vb[kt][0]);
                    mma_tf32(o[mt][1], a, vb[kt][1]);
                }
        }
        __syncthreads();
    }

    // write unnormalized partials + partial sums
    #pragma unroll
    for (int mt = 0; mt < 2; mt++)
        #pragma unroll
        for (int hf = 0; hf < 2; hf++){
            float l = lsum[mt][hf];
            l += __shfl_xor_sync(0xffffffffu, l, 1);
            l += __shfl_xor_sync(0xffffffffu, l, 2);
            if (lc == 0){
                int row = qrow0 + mt*16 + lq + hf*8;
                g_LP[kh][row*8 + h] = l;
            }
        }
    float* OP = g_OP[kh];
    #pragma unroll
    for (int mt = 0; mt < 2; mt++)
        #pragma unroll
        for (int d = 0; d < 2; d++){
            float* op = OP + (size_t)(qrow0 + mt*16 + lq)*E_ + hoff + d*8 + 2*lc;
            *(float2*)op = make_float2(o[mt][d][0], o[mt][d][1]);
            *(float2*)(op + 8*E_) = make_float2(o[mt][d][2], o[mt][d][3]);
        }
}

// ---------------- combine split-key partials -> g_AT --------------------------
__global__ void k_combine(){
    int e = blockIdx.x*256 + threadIdx.x;  // float4 index over TOK_*E_/4
    int row = e >> 5; int c4 = e & 31; int head = c4 >> 2;
    float l0 = g_LP[0][row*8 + head], l1 = g_LP[1][row*8 + head];
    float inv = 1.f / (l0 + l1);
    const float4* a = (const float4*)(g_OP[0] + (size_t)row*E_) + c4;
    const float4* bb = (const float4*)(g_OP[1] + (size_t)row*E_) + c4;
    float4 va = *a, vb = *bb;
    float4 r;
    r.x = (va.x + vb.x)*inv;
    r.y = (va.y + vb.y)*inv;
    r.z = (va.z + vb.z)*inv;
    r.w = (va.w + vb.w)*inv;
    ((float4*)(g_AT + (size_t)row*E_))[c4] = r;
}

// ---------------- residual + LayerNorm (row = 128) ----------------
__global__ void k_lnres(int aId, int rId, const float* __restrict__ g,
                        const float* __restrict__ be, int oId){
    const float* A = bufptr(aId);
    const float* R = bufptr(rId);
    float* out = bufptr(oId);
    int tid = threadIdx.x; int warp = tid >> 5, lane = tid & 31;
    int row = blockIdx.x*8 + warp;
    float v[4];
    #pragma unroll
    for (int i = 0; i < 4; i++){
        int e = i*32 + lane;
        v[i] = A[(size_t)row*E_ + e] + R[(size_t)row*E_ + e];
    }
    float s  = v[0]+v[1]+v[2]+v[3];
    float s2 = v[0]*v[0]+v[1]*v[1]+v[2]*v[2]+v[3]*v[3];
    #pragma unroll
    for (int off = 16; off; off >>= 1){
        s  += __shfl_xor_sync(0xffffffffu, s,  off);
        s2 += __shfl_xor_sync(0xffffffffu, s2, off);
    }
    float mean = s * (1.f/128.f);
    float var  = s2 * (1.f/128.f) - mean*mean;
    float rs = rsqrtf(var + 1e-5f);
    #pragma unroll
    for (int i = 0; i < 4; i++){
        int e = i*32 + lane;
        out[(size_t)row*E_ + e] = (v[i]-mean)*rs*g[e] + be[e];
    }
}

// ---------------- final projection: split-K over 65536 (fp32) -----------------
__global__ void k_splitk(const float* __restrict__ W){
    __shared__ float Zs[16*32];
    __shared__ float Ws_[32*129];
    int t = threadIdx.x;
    int kb = blockIdx.x * KCSZ_;
    int o = t & 127;
    int bset = t >> 7;
    float acc[8];
    #pragma unroll
    for (int i = 0; i < 8; i++) acc[i] = 0.f;
    for (int k0 = 0; k0 < KCSZ_; k0 += 32){
        #pragma unroll
        for (int i = 0; i < 2; i++){
            int e = t + i*256; int b_ = e >> 5, kk = e & 31;
            Zs[b_*32 + kk] = g_Z[(size_t)b_*KOUT_ + kb + k0 + kk];
        }
        #pragma unroll
        for (int i = 0; i < 16; i++){
            int e = t + i*256; int oo = e >> 5, kk = e & 31;
            Ws_[kk*129 + oo] = W[(size_t)oo*KOUT_ + kb + k0 + kk];
        }
        __syncthreads();
        #pragma unroll
        for (int kk = 0; kk < 32; kk++){
            float w = Ws_[kk*129 + o];
            #pragma unroll
            for (int i = 0; i < 8; i++)
                acc[i] += Zs[(bset*8 + i)*32 + kk] * w;
        }
        __syncthreads();
    }
    #pragma unroll
    for (int i = 0; i < 8; i++)
        g_PART[blockIdx.x*2048 + (bset*8 + i)*128 + o] = acc[i];
}

__global__ void k_reduce(const float* __restrict__ bout, float* __restrict__ out){
    int e = blockIdx.x*256 + threadIdx.x;   // 0..2047
    float s = bout[e & 127];
    #pragma unroll 8
    for (int c = 0; c < KCHUNKS_; c++) s += g_PART[c*2048 + e];
    out[e] = s;
}

// ---------------- launch ----------------
extern "C" void kernel_launch(void* const* d_in, const int* in_sizes, int n_in,
                              void* d_out, int out_size){
    const float* x    = (const float*)d_in[0];
    const float* prot = (const float*)d_in[1];
    const float* Wemb = (const float*)d_in[2];
    const float* bemb = (const float*)d_in[3];
    const float* Wpro = (const float*)d_in[4];
    const float* bpro = (const float*)d_in[5];
    const float* inw  = (const float*)d_in[6];
    const float* inb  = (const float*)d_in[7];
    const float* ow   = (const float*)d_in[8];
    const float* ob   = (const float*)d_in[9];
    const float* W1   = (const float*)d_in[10];
    const float* b1   = (const float*)d_in[11];
    const float* W2   = (const float*)d_in[12];
    const float* b2   = (const float*)d_in[13];
    const float* g1   = (const float*)d_in[14];
    const float* be1  = (const float*)d_in[15];
    const float* g2   = (const float*)d_in[16];
    const float* be2  = (const float*)d_in[17];
    const float* Wout = (const float*)d_in[18];
    const float* bout = (const float*)d_in[19];
    float* out = (float*)d_out;

    k_rowprep<<<1024, 256>>>(x, prot, Wemb, bemb, Wpro, bpro);
    k_mmagemm<0,0,128,1><<<dim3(TOK_/128, 2), 256>>>(0, inw, inb, 2, 128);
    k_mmagemm<0,1,128,2><<<dim3(KVN_/128, 4), 256>>>(0, inw + 128*E_, inb + 128, 3, 256);
    k_attn<<<B_*H_*4, 256>>>();
    k_combine<<<TOK_*E_/4/256, 256>>>();
    k_mmagemm<0,0,128,0><<<dim3(TOK_/128, 2), 256>>>(4, ow, ob, 5, 128);
    k_lnres<<<TOK_/8, 256>>>(0, 5, g1, be1, 6);
    k_mmagemm<1,0,128,0><<<dim3(TOK_/128, 1), 256>>>(6, W1, b1, 7, 64);
    k_mmagemm<0,0,64,0><<<dim3(TOK_/128, 2), 256>>>(7, W2, b2, 8, 128);
    k_lnres<<<TOK_/8, 256>>>(6, 8, g2, be2, 9);
    k_splitk<<<KCHUNKS_, 256>>>(Wout);
    k_reduce<<<8, 256>>>(bout, out);
}

// round 15
// speedup vs baseline: 1.1542x; 1.1542x over previous
#include <cuda_runtime.h>

// ---------------- problem constants ----------------
#define B_      16
#define N_      64
#define P_      6
#define D_      8
#define E_      128
#define H_      8
#define HD_     16
#define S_      512            // N*D tokens per batch
#define TOK_    (B_*S_)        // 8192
#define KVN_    (B_*2*S_)      // 16384
#define NPROTO_ 256            // D * 32 prototype rows
#define I_      64
#define O_      128
#define KOUT_   (S_*E_)        // 65536
#define KCHUNKS_ 256
#define KCSZ_   (KOUT_/KCHUNKS_) // 256

// ---------------- device scratch (no allocations allowed) ----------------
__device__ float g_IE  [TOK_*E_];
__device__ float g_PE  [TOK_*E_];
__device__ float g_Q   [TOK_*E_];     // tf32 bit patterns (attention-only)
__device__ float g_KVO [KVN_*2*E_];   // tf32 bit patterns; cols 0..127 K, 128..255 V
__device__ float g_AT  [TOK_*E_];
__device__ float g_AP  [TOK_*E_];
__device__ float g_H1  [TOK_*E_];
__device__ float g_F1  [TOK_*I_];
__device__ float g_F2  [TOK_*E_];
__device__ float g_Z   [TOK_*E_];
__device__ float g_PART[KCHUNKS_*B_*O_];
__device__ float g_QN  [TOK_*H_];     // per (qrow, head) L2 norm
__device__ float g_KMAX[B_*H_];       // per (b, head) max key norm^2 (bits, atomicMax)

__device__ __forceinline__ float* bufptr(int id){
    switch(id){
        case 0: return g_IE;
        case 2: return g_Q;
        case 3: return g_KVO;
        case 4: return g_AT;
        case 5: return g_AP;
        case 6: return g_H1;
        case 7: return g_F1;
        case 8: return g_F2;
        default: return g_Z;
    }
}

// ---------------- mma helpers ----------------
__device__ __forceinline__ unsigned f2tf(float f){
    unsigned r; asm("cvt.rna.tf32.f32 %0, %1;" : "=r"(r) : "f"(f)); return r;
}
__device__ __forceinline__ unsigned pack_h2(float lo, float hi){
    unsigned r; asm("cvt.rn.f16x2.f32 %0, %1, %2;" : "=r"(r) : "f"(hi), "f"(lo)); return r;
}
__device__ __forceinline__ void mma_tf32(float c[4], const unsigned a[4], const unsigned b[2]){
    asm volatile("mma.sync.aligned.m16n8k8.row.col.f32.tf32.tf32.f32 "
        "{%0,%1,%2,%3}, {%4,%5,%6,%7}, {%8,%9}, {%0,%1,%2,%3};"
        : "+f"(c[0]), "+f"(c[1]), "+f"(c[2]), "+f"(c[3])
        : "r"(a[0]), "r"(a[1]), "r"(a[2]), "r"(a[3]), "r"(b[0]), "r"(b[1]));
}
__device__ __forceinline__ void mma_f16(float c[4], const unsigned a[4], const unsigned b[2]){
    asm volatile("mma.sync.aligned.m16n8k16.row.col.f32.f16.f16.f32 "
        "{%0,%1,%2,%3}, {%4,%5,%6,%7}, {%8,%9}, {%0,%1,%2,%3};"
        : "+f"(c[0]), "+f"(c[1]), "+f"(c[2]), "+f"(c[3])
        : "r"(a[0]), "r"(a[1]), "r"(a[2]), "r"(a[3]), "r"(b[0]), "r"(b[1]));
}

// ---------------- rowprep: proto inorm (in-block) + x inorm + argmax + embeds ----
__global__ void k_rowprep(const float* __restrict__ x, const float* __restrict__ proto,
                          const float* __restrict__ Wemb, const float* __restrict__ bemb,
                          const float* __restrict__ Wpro, const float* __restrict__ bpro){
    __shared__ float sPN  [NPROTO_*P_];
    __shared__ float sPNL2[NPROTO_*P_];
    __shared__ float sWe[E_*P_];
    __shared__ float sWp[E_*P_];
    __shared__ float sbe[E_];
    __shared__ float sbp[E_];
    int tid = threadIdx.x;
    if (blockIdx.x == 0 && tid < B_*H_) g_KMAX[tid] = 0.f;
    {
        float v[P_]; float s = 0.f;
        #pragma unroll
        for (int p = 0; p < P_; p++){ v[p] = proto[tid*P_ + p]; s += v[p]; }
        float m = s * (1.f/P_);
        float var = 0.f;
        #pragma unroll
        for (int p = 0; p < P_; p++){ float dd = v[p]-m; var += dd*dd; }
        var *= (1.f/P_);
        float rs = rsqrtf(var + 1e-5f);
        float nrm = 0.f;
        #pragma unroll
        for (int p = 0; p < P_; p++){ v[p] = (v[p]-m)*rs; nrm += v[p]*v[p]; sPN[tid*P_+p] = v[p]; }
        float inv = 1.f / fmaxf(sqrtf(nrm), 1e-12f);
        #pragma unroll
        for (int p = 0; p < P_; p++) sPNL2[tid*P_+p] = v[p]*inv;
    }
    for (int i = tid; i < E_*P_; i += 256){ sWe[i] = Wemb[i]; sWp[i] = Wpro[i]; }
    if (tid < E_){ sbe[tid] = bemb[tid]; sbp[tid] = bpro[tid]; }
    __syncthreads();

    int warp = tid >> 5, lane = tid & 31;
    int r = blockIdx.x*8 + warp;
    int b = r >> 9; int n = (r >> 3) & 63; int d = r & 7;
    const float* xp = x + ((b*64 + n)*6)*8 + d;

    float v[6]; float s = 0.f;
    #pragma unroll
    for (int p = 0; p < 6; p++){ v[p] = xp[p*8]; s += v[p]; }
    float mean = s * (1.f/6.f);
    float var = 0.f;
    #pragma unroll
    for (int p = 0; p < 6; p++){ float dd = v[p]-mean; var += dd*dd; }
    var *= (1.f/6.f);
    float rs = rsqrtf(var + 1e-5f);
    float xn[6];
    #pragma unroll
    for (int p = 0; p < 6; p++) xn[p] = (v[p]-mean)*rs;

    float best = -1e30f; int bi = 0;
    #pragma unroll
    for (int i = 0; i < 8; i++){
        int pidx = i*32 + lane;
        const float* pr = &sPNL2[pidx*6];
        float sim = xn[0]*pr[0] + xn[1]*pr[1] + xn[2]*pr[2]
                  + xn[3]*pr[3] + xn[4]*pr[4] + xn[5]*pr[5];
        if (sim > best){ best = sim; bi = pidx; }
    }
    #pragma unroll
    for (int off = 16; off; off >>= 1){
        float ov = __shfl_xor_sync(0xffffffffu, best, off);
        int   oi = __shfl_xor_sync(0xffffffffu, bi,   off);
        if (ov > best || (ov == best && oi < bi)){ best = ov; bi = oi; }
    }

    float sel[6];
    #pragma unroll
    for (int p = 0; p < 6; p++) sel[p] = sPN[bi*6 + p];

    #pragma unroll
    for (int e4 = 0; e4 < 4; e4++){
        int e = e4*32 + lane;
        const float* we = &sWe[e*6];
        const float* wp = &sWp[e*6];
        float a1 = sbe[e], a2 = sbp[e];
        #pragma unroll
        for (int p = 0; p < 6; p++){ a1 += xn[p]*we[p]; a2 += sel[p]*wp[p]; }
        g_IE[r*E_ + e] = a1;
        g_PE[r*E_ + e] = a2;
    }
}

// ---------------- tf32 tensor-core GEMM, fragment-major smem ------------------
// EPI: 0 = plain fp32 store; 1 = tf32-bit store + q-norm; 2 = tf32-bit store + kmax.
template<int RELU, int CONCAT, int KK, int EPI>
__global__ void __launch_bounds__(256) k_mmagemm(int aId, const float* __restrict__ W,
                        const float* __restrict__ bias, int cId, int Nn){
    __shared__ __align__(16) unsigned sA[32*132];
    __shared__ __align__(16) unsigned sW[32*66];
    float* C = bufptr(cId);
    int t = threadIdx.x;
    int m0 = blockIdx.x * 128, n0 = blockIdx.y * 64;
    const float* Abase;
    if (CONCAT){
        int bb = m0 >> 10, j = m0 & 1023;
        Abase = ((j < 512) ? g_IE : g_PE) + (size_t)(bb*512 + (j & 511)) * KK;
    } else {
        Abase = bufptr(aId) + (size_t)m0 * KK;
    }
    int lane = t & 31, warp = t >> 5;
    int wm = warp >> 1, wn = warp & 1;
    int lq = lane >> 2, lc = lane & 3;
    int arow = t >> 3, ac4 = (t & 7)*4;
    int ksld = ac4 >> 3;
    int aslot = 2*((ac4 >> 2) & 1);
    int bslot = (ac4 >> 2) & 1;

    float c[2][4][4];
    #pragma unroll
    for (int mt = 0; mt < 2; mt++)
        #pragma unroll
        for (int nt = 0; nt < 4; nt++)
            c[mt][nt][0]=c[mt][nt][1]=c[mt][nt][2]=c[mt][nt][3]=0.f;

    float4 pa[4], pw[2];
    #pragma unroll
    for (int i = 0; i < 4; i++)
        pa[i] = *(const float4*)&Abase[(size_t)(arow + i*32)*KK + ac4];
    #pragma unroll
    for (int i = 0; i < 2; i++)
        pw[i] = *(const float4*)&W[(size_t)(n0 + arow + i*32)*KK + ac4];

    for (int k0 = 0; k0 < KK; k0 += 32){
        #pragma unroll
        for (int i = 0; i < 4; i++){
            int row = arow + i*32;
            int fa = (row >> 4)*4 + ksld;
            unsigned* d = &sA[fa*132 + (row & 7)*16 + ((row >> 3) & 1) + aslot];
            d[0]=f2tf(pa[i].x); d[4]=f2tf(pa[i].y); d[8]=f2tf(pa[i].z); d[12]=f2tf(pa[i].w);
        }
        #pragma unroll
        for (int i = 0; i < 2; i++){
            int row = arow + i*32;
            int fb = (row >> 3)*4 + ksld;
            unsigned* d = &sW[fb*66 + (row & 7)*8 + bslot];
            d[0]=f2tf(pw[i].x); d[2]=f2tf(pw[i].y); d[4]=f2tf(pw[i].z); d[6]=f2tf(pw[i].w);
        }
        __syncthreads();
        if (k0 + 32 < KK){
            #pragma unroll
            for (int i = 0; i < 4; i++)
                pa[i] = *(const float4*)&Abase[(size_t)(arow + i*32)*KK + k0 + 32 + ac4];
            #pragma unroll
            for (int i = 0; i < 2; i++)
                pw[i] = *(const float4*)&W[(size_t)(n0 + arow + i*32)*KK + k0 + 32 + ac4];
        }
        #pragma unroll
        for (int ks = 0; ks < 4; ks++){
            unsigned a[2][4], bf[4][2];
            #pragma unroll
            for (int mt = 0; mt < 2; mt++)
                *(uint4*)a[mt] = *(const uint4*)&sA[((2*wm + mt)*4 + ks)*132 + lane*4];
            #pragma unroll
            for (int nt = 0; nt < 4; nt++)
                *(uint2*)bf[nt] = *(const uint2*)&sW[((4*wn + nt)*4 + ks)*66 + lane*2];
            #pragma unroll
            for (int mt = 0; mt < 2; mt++)
                #pragma unroll
                for (int nt = 0; nt < 4; nt++)
                    mma_tf32(c[mt][nt], a[mt], bf[nt]);
        }
        __syncthreads();
    }
    #pragma unroll
    for (int nt = 0; nt < 4; nt++){
        int col = n0 + wn*32 + nt*8 + 2*lc;
        float b0 = bias[col], b1 = bias[col+1];
        #pragma unroll
        for (int mt = 0; mt < 2; mt++){
            int row = m0 + wm*32 + mt*16 + lq;
            float v0 = c[mt][nt][0] + b0, v1 = c[mt][nt][1] + b1;
            float v2 = c[mt][nt][2] + b0, v3 = c[mt][nt][3] + b1;
            if (RELU){
                v0 = fmaxf(v0,0.f); v1 = fmaxf(v1,0.f);
                v2 = fmaxf(v2,0.f); v3 = fmaxf(v3,0.f);
            }
            if (EPI == 0){
                *(float2*)&C[(size_t)row*Nn + col]     = make_float2(v0, v1);
                *(float2*)&C[(size_t)(row+8)*Nn + col] = make_float2(v2, v3);
            } else {
                *(float2*)&C[(size_t)row*Nn + col] = make_float2(
                    __uint_as_float(f2tf(v0)), __uint_as_float(f2tf(v1)));
                *(float2*)&C[(size_t)(row+8)*Nn + col] = make_float2(
                    __uint_as_float(f2tf(v2)), __uint_as_float(f2tf(v3)));
            }
            c[mt][nt][0]=v0; c[mt][nt][1]=v1; c[mt][nt][2]=v2; c[mt][nt][3]=v3;
        }
    }
    if (EPI == 1){
        #pragma unroll
        for (int p = 0; p < 2; p++){
            int head = (n0 >> 4) + wn*2 + p;
            #pragma unroll
            for (int mt = 0; mt < 2; mt++){
                float s0 = 0.f, s1 = 0.f;
                #pragma unroll
                for (int q = 0; q < 2; q++){
                    int nt = 2*p + q;
                    s0 += c[mt][nt][0]*c[mt][nt][0] + c[mt][nt][1]*c[mt][nt][1];
                    s1 += c[mt][nt][2]*c[mt][nt][2] + c[mt][nt][3]*c[mt][nt][3];
                }
                s0 += __shfl_xor_sync(0xffffffffu, s0, 1);
                s0 += __shfl_xor_sync(0xffffffffu, s0, 2);
                s1 += __shfl_xor_sync(0xffffffffu, s1, 1);
                s1 += __shfl_xor_sync(0xffffffffu, s1, 2);
                if (lc == 0){
                    int row = m0 + wm*32 + mt*16 + lq;
                    g_QN[row*8 + head]     = sqrtf(s0);
                    g_QN[(row+8)*8 + head] = sqrtf(s1);
                }
            }
        }
    }
    if (EPI == 2 && n0 < 128){
        int bb = m0 >> 10;
        #pragma unroll
        for (int p = 0; p < 2; p++){
            int head = (n0 >> 4) + wn*2 + p;
            float mx = 0.f;
            #pragma unroll
            for (int mt = 0; mt < 2; mt++){
                float s0 = 0.f, s1 = 0.f;
                #pragma unroll
                for (int q = 0; q < 2; q++){
                    int nt = 2*p + q;
                    s0 += c[mt][nt][0]*c[mt][nt][0] + c[mt][nt][1]*c[mt][nt][1];
                    s1 += c[mt][nt][2]*c[mt][nt][2] + c[mt][nt][3]*c[mt][nt][3];
                }
                s0 += __shfl_xor_sync(0xffffffffu, s0, 1);
                s0 += __shfl_xor_sync(0xffffffffu, s0, 2);
                s1 += __shfl_xor_sync(0xffffffffu, s1, 1);
                s1 += __shfl_xor_sync(0xffffffffu, s1, 2);
                mx = fmaxf(mx, fmaxf(s0, s1));
            }
            #pragma unroll
            for (int off = 16; off; off >>= 1)
                mx = fmaxf(mx, __shfl_xor_sync(0xffffffffu, mx, off));
            if (lane == 0)
                atomicMax((unsigned*)&g_KMAX[bb*8 + head], __float_as_uint(mx));
        }
    }
}

// ---------------- attention: fp16 P·V (zero-shuffle C->A), 32 q rows/warp -----
// grid = B*H*2; 8 warps/block. QK in tf32 mma; P packed to f16x2 straight from
// the C-fragment; V B-frags built from smem (stride 28 -> conflict-free).
__global__ void __launch_bounds__(256) k_attn(){
    __shared__ unsigned sK[32*20];
    __shared__ float    sV[32*28];
    int blk = blockIdx.x;                 // 0..255
    int bh = blk >> 1, qh = blk & 1;
    int b = bh >> 3, h = bh & 7;
    int t = threadIdx.x;
    int lane = t & 31, warp = t >> 5;
    int lq = lane >> 2, lc = lane & 3;
    int qrow0 = b*512 + qh*256 + warp*32;
    int hoff = h*16;
    const unsigned* Qb  = (const unsigned*)(g_Q  + (size_t)qrow0*E_ + hoff);
    const unsigned* KVb = (const unsigned*)(g_KVO + (size_t)(b*1024)*256);

    unsigned qa[2][2][4];
    #pragma unroll
    for (int mt = 0; mt < 2; mt++)
        #pragma unroll
        for (int ks = 0; ks < 2; ks++){
            const unsigned* qp = Qb + (size_t)(mt*16)*E_ + ks*8;
            qa[mt][ks][0] = qp[(size_t)lq*E_     + lc];
            qa[mt][ks][1] = qp[(size_t)(lq+8)*E_ + lc];
            qa[mt][ks][2] = qp[(size_t)lq*E_     + lc+4];
            qa[mt][ks][3] = qp[(size_t)(lq+8)*E_ + lc+4];
        }

    float kmax = sqrtf(g_KMAX[bh]);
    float mb[2][2];
    #pragma unroll
    for (int mt = 0; mt < 2; mt++){
        mb[mt][0] = g_QN[(qrow0 + mt*16 + lq  )*8 + h] * kmax * 0.25f;
        mb[mt][1] = g_QN[(qrow0 + mt*16 + lq+8)*8 + h] * kmax * 0.25f;
    }

    float o[2][2][4];
    #pragma unroll
    for (int mt = 0; mt < 2; mt++)
        #pragma unroll
        for (int d = 0; d < 2; d++)
            o[mt][d][0]=o[mt][d][1]=o[mt][d][2]=o[mt][d][3]=0.f;
    float lsum[2][2] = {};

    int sj = t >> 3, sf = t & 7;
    int scol = (sf & 3)*4;

    #pragma unroll 1
    for (int key0 = 0; key0 < 1024; key0 += 32){
        {
            const unsigned* src = KVb + (size_t)(key0 + sj)*256 +
                               ((sf < 4) ? (hoff + scol) : (128 + hoff + scol));
            uint4 v = *(const uint4*)src;
            if (sf < 4) *(uint4*)&sK[sj*20 + scol] = v;
            else        *(uint4*)&sV[sj*28 + scol] = v;
        }
        __syncthreads();

        #pragma unroll
        for (int sub = 0; sub < 2; sub++){
            int r16 = sub*16;
            unsigned kb[2][2][2];
            #pragma unroll
            for (int nt = 0; nt < 2; nt++)
                #pragma unroll
                for (int ks = 0; ks < 2; ks++){
                    const unsigned* kp = &sK[(r16 + nt*8 + lq)*20 + ks*8 + lc];
                    kb[nt][ks][0] = kp[0];
                    kb[nt][ks][1] = kp[4];
                }
            float s[2][2][4];
            #pragma unroll
            for (int mt = 0; mt < 2; mt++)
                #pragma unroll
                for (int nt = 0; nt < 2; nt++){
                    s[mt][nt][0]=s[mt][nt][1]=s[mt][nt][2]=s[mt][nt][3]=0.f;
                    mma_tf32(s[mt][nt], qa[mt][0], kb[nt][0]);
                    mma_tf32(s[mt][nt], qa[mt][1], kb[nt][1]);
                }
            #pragma unroll
            for (int mt = 0; mt < 2; mt++)
                #pragma unroll
                for (int nt = 0; nt < 2; nt++){
                    float q0 = __expf(s[mt][nt][0]*0.25f - mb[mt][0]);
                    float q1 = __expf(s[mt][nt][1]*0.25f - mb[mt][0]);
                    float q2 = __expf(s[mt][nt][2]*0.25f - mb[mt][1]);
                    float q3 = __expf(s[mt][nt][3]*0.25f - mb[mt][1]);
                    s[mt][nt][0]=q0; s[mt][nt][1]=q1; s[mt][nt][2]=q2; s[mt][nt][3]=q3;
                    lsum[mt][0] += q0 + q1;
                    lsum[mt][1] += q2 + q3;
                }
            // V B-frags for m16n8k16: rows = keys {2lc,2lc+1,2lc+8,2lc+9}
            unsigned vb[2][2];
            #pragma unroll
            for (int d = 0; d < 2; d++){
                int col = d*8 + lq;
                float v0 = sV[(r16 + 2*lc    )*28 + col];
                float v1 = sV[(r16 + 2*lc + 1)*28 + col];
                float v2 = sV[(r16 + 2*lc + 8)*28 + col];
                float v3 = sV[(r16 + 2*lc + 9)*28 + col];
                vb[d][0] = pack_h2(v0, v1);
                vb[d][1] = pack_h2(v2, v3);
            }
            // P A-frags: direct pack of C-fragments (no shuffles)
            #pragma unroll
            for (int mt = 0; mt < 2; mt++){
                unsigned pa[4];
                pa[0] = pack_h2(s[mt][0][0], s[mt][0][1]);
                pa[1] = pack_h2(s[mt][0][2], s[mt][0][3]);
                pa[2] = pack_h2(s[mt][1][0], s[mt][1][1]);
                pa[3] = pack_h2(s[mt][1][2], s[mt][1][3]);
                mma_f16(o[mt][0], pa, vb[0]);
                mma_f16(o[mt][1], pa, vb[1]);
            }
        }
        __syncthreads();
    }

    float inv[2][2];
    #pragma unroll
    for (int mt = 0; mt < 2; mt++)
        #pragma unroll
        for (int hf = 0; hf < 2; hf++){
            float l = lsum[mt][hf];
            l += __shfl_xor_sync(0xffffffffu, l, 1);
            l += __shfl_xor_sync(0xffffffffu, l, 2);
            inv[mt][hf] = 1.f / l;
        }
    #pragma unroll
    for (int mt = 0; mt < 2; mt++)
        #pragma unroll
        for (int d = 0; d < 2; d++){
            float* op = g_AT + (size_t)(qrow0 + mt*16 + lq)*E_ + hoff + d*8 + 2*lc;
            *(float2*)op = make_float2(o[mt][d][0]*inv[mt][0], o[mt][d][1]*inv[mt][0]);
            *(float2*)(op + 8*E_) = make_float2(o[mt][d][2]*inv[mt][1], o[mt][d][3]*inv[mt][1]);
        }
}

// ---------------- residual + LayerNorm (row = 128) ----------------
__global__ void k_lnres(int aId, int rId, const float* __restrict__ g,
                        const float* __restrict__ be, int oId){
    const float* A = bufptr(aId);
    const float* R = bufptr(rId);
    float* out = bufptr(oId);
    int tid = threadIdx.x; int warp = tid >> 5, lane = tid & 31;
    int row = blockIdx.x*8 + warp;
    float v[4];
    #pragma unroll
    for (int i = 0; i < 4; i++){
        int e = i*32 + lane;
        v[i] = A[(size_t)row*E_ + e] + R[(size_t)row*E_ + e];
    }
    float s  = v[0]+v[1]+v[2]+v[3];
    float s2 = v[0]*v[0]+v[1]*v[1]+v[2]*v[2]+v[3]*v[3];
    #pragma unroll
    for (int off = 16; off; off >>= 1){
        s  += __shfl_xor_sync(0xffffffffu, s,  off);
        s2 += __shfl_xor_sync(0xffffffffu, s2, off);
    }
    float mean = s * (1.f/128.f);
    float var  = s2 * (1.f/128.f) - mean*mean;
    float rs = rsqrtf(var + 1e-5f);
    #pragma unroll
    for (int i = 0; i < 4; i++){
        int e = i*32 + lane;
        out[(size_t)row*E_ + e] = (v[i]-mean)*rs*g[e] + be[e];
    }
}

// ---------------- final projection: split-K over 65536 (fp32) -----------------
__global__ void k_splitk(const float* __restrict__ W){
    __shared__ float Zs[16*32];
    __shared__ float Ws_[32*129];
    int t = threadIdx.x;
    int kb = blockIdx.x * KCSZ_;
    int o = t & 127;
    int bset = t >> 7;
    float acc[8];
    #pragma unroll
    for (int i = 0; i < 8; i++) acc[i] = 0.f;
    for (int k0 = 0; k0 < KCSZ_; k0 += 32){
        #pragma unroll
        for (int i = 0; i < 2; i++){
            int e = t + i*256; int b_ = e >> 5, kk = e & 31;
            Zs[b_*32 + kk] = g_Z[(size_t)b_*KOUT_ + kb + k0 + kk];
        }
        #pragma unroll
        for (int i = 0; i < 16; i++){
            int e = t + i*256; int oo = e >> 5, kk = e & 31;
            Ws_[kk*129 + oo] = W[(size_t)oo*KOUT_ + kb + k0 + kk];
        }
        __syncthreads();
        #pragma unroll
        for (int kk = 0; kk < 32; kk++){
            float w = Ws_[kk*129 + o];
            #pragma unroll
            for (int i = 0; i < 8; i++)
                acc[i] += Zs[(bset*8 + i)*32 + kk] * w;
        }
        __syncthreads();
    }
    #pragma unroll
    for (int i = 0; i < 8; i++)
        g_PART[blockIdx.x*2048 + (bset*8 + i)*128 + o] = acc[i];
}

__global__ void k_reduce(const float* __restrict__ bout, float* __restrict__ out){
    int e = blockIdx.x*256 + threadIdx.x;   // 0..2047
    float s = bout[e & 127];
    #pragma unroll 8
    for (int c = 0; c < KCHUNKS_; c++) s += g_PART[c*2048 + e];
    out[e] = s;
}

// ---------------- launch ----------------
extern "C" void kernel_launch(void* const* d_in, const int* in_sizes, int n_in,
                              void* d_out, int out_size){
    const float* x    = (const float*)d_in[0];
    const float* prot = (const float*)d_in[1];
    const float* Wemb = (const float*)d_in[2];
    const float* bemb = (const float*)d_in[3];
    const float* Wpro = (const float*)d_in[4];
    const float* bpro = (const float*)d_in[5];
    const float* inw  = (const float*)d_in[6];
    const float* inb  = (const float*)d_in[7];
    const float* ow   = (const float*)d_in[8];
    const float* ob   = (const float*)d_in[9];
    const float* W1   = (const float*)d_in[10];
    const float* b1   = (const float*)d_in[11];
    const float* W2   = (const float*)d_in[12];
    const float* b2   = (const float*)d_in[13];
    const float* g1   = (const float*)d_in[14];
    const float* be1  = (const float*)d_in[15];
    const float* g2   = (const float*)d_in[16];
    const float* be2  = (const float*)d_in[17];
    const float* Wout = (const float*)d_in[18];
    const float* bout = (const float*)d_in[19];
    float* out = (float*)d_out;

    k_rowprep<<<1024, 256>>>(x, prot, Wemb, bemb, Wpro, bpro);
    k_mmagemm<0,0,128,1><<<dim3(TOK_/128, 2), 256>>>(0, inw, inb, 2, 128);
    k_mmagemm<0,1,128,2><<<dim3(KVN_/128, 4), 256>>>(0, inw + 128*E_, inb + 128, 3, 256);
    k_attn<<<B_*H_*2, 256>>>();
    k_mmagemm<0,0,128,0><<<dim3(TOK_/128, 2), 256>>>(4, ow, ob, 5, 128);
    k_lnres<<<TOK_/8, 256>>>(0, 5, g1, be1, 6);
    k_mmagemm<1,0,128,0><<<dim3(TOK_/128, 1), 256>>>(6, W1, b1, 7, 64);
    k_mmagemm<0,0,64,0><<<dim3(TOK_/128, 2), 256>>>(7, W2, b2, 8, 128);
    k_lnres<<<TOK_/8, 256>>>(6, 8, g2, be2, 9);
    k_splitk<<<KCHUNKS_, 256>>>(Wout);
    k_reduce<<<8, 256>>>(bout, out);
}

// round 16
// speedup vs baseline: 1.1884x; 1.0296x over previous
#include <cuda_runtime.h>

// ---------------- problem constants ----------------
#define B_      16
#define N_      64
#define P_      6
#define D_      8
#define E_      128
#define H_      8
#define HD_     16
#define S_      512            // N*D tokens per batch
#define TOK_    (B_*S_)        // 8192
#define KVN_    (B_*2*S_)      // 16384
#define NPROTO_ 256            // D * 32 prototype rows
#define I_      64
#define O_      128
#define KOUT_   (S_*E_)        // 65536
#define KCHUNKS_ 256
#define KCSZ_   (KOUT_/KCHUNKS_) // 256
#define QSCALE_ (0.25f*1.4426950408889634f)   // fold 1/sqrt(Hd) and log2e into Q

// ---------------- device scratch (no allocations allowed) ----------------
__device__ float g_IE  [TOK_*E_];
__device__ float g_PE  [TOK_*E_];
__device__ float g_Q   [TOK_*E_];     // tf32 bits of q*QSCALE (attention-only)
__device__ float g_KVO [KVN_*2*E_];   // tf32 bits; cols 0..127 K, 128..255 V
__device__ float g_AT  [TOK_*E_];
__device__ float g_AP  [TOK_*E_];
__device__ float g_H1  [TOK_*E_];
__device__ float g_F1  [TOK_*I_];
__device__ float g_F2  [TOK_*E_];
__device__ float g_Z   [TOK_*E_];
__device__ float g_PART[KCHUNKS_*B_*O_];
__device__ float g_QN  [TOK_*H_];     // per (qrow, head) L2 norm of SCALED q
__device__ float g_KMAX[B_*H_];       // per (b, head) max key norm^2 (bits, atomicMax)

__device__ __forceinline__ float* bufptr(int id){
    switch(id){
        case 0: return g_IE;
        case 2: return g_Q;
        case 3: return g_KVO;
        case 4: return g_AT;
        case 5: return g_AP;
        case 6: return g_H1;
        case 7: return g_F1;
        case 8: return g_F2;
        default: return g_Z;
    }
}

// ---------------- mma helpers ----------------
__device__ __forceinline__ unsigned f2tf(float f){
    unsigned r; asm("cvt.rna.tf32.f32 %0, %1;" : "=r"(r) : "f"(f)); return r;
}
__device__ __forceinline__ unsigned pack_h2(float lo, float hi){
    unsigned r; asm("cvt.rn.f16x2.f32 %0, %1, %2;" : "=r"(r) : "f"(hi), "f"(lo)); return r;
}
__device__ __forceinline__ float ex2(float x){
    float r; asm("ex2.approx.f32 %0, %1;" : "=f"(r) : "f"(x)); return r;
}
__device__ __forceinline__ void mma_tf32(float c[4], const unsigned a[4], const unsigned b[2]){
    asm volatile("mma.sync.aligned.m16n8k8.row.col.f32.tf32.tf32.f32 "
        "{%0,%1,%2,%3}, {%4,%5,%6,%7}, {%8,%9}, {%0,%1,%2,%3};"
        : "+f"(c[0]), "+f"(c[1]), "+f"(c[2]), "+f"(c[3])
        : "r"(a[0]), "r"(a[1]), "r"(a[2]), "r"(a[3]), "r"(b[0]), "r"(b[1]));
}
__device__ __forceinline__ void mma_f16(float c[4], const unsigned a[4], const unsigned b[2]){
    asm volatile("mma.sync.aligned.m16n8k16.row.col.f32.f16.f16.f32 "
        "{%0,%1,%2,%3}, {%4,%5,%6,%7}, {%8,%9}, {%0,%1,%2,%3};"
        : "+f"(c[0]), "+f"(c[1]), "+f"(c[2]), "+f"(c[3])
        : "r"(a[0]), "r"(a[1]), "r"(a[2]), "r"(a[3]), "r"(b[0]), "r"(b[1]));
}

// ---------------- rowprep: proto inorm (in-block) + x inorm + argmax + embeds ----
__global__ void k_rowprep(const float* __restrict__ x, const float* __restrict__ proto,
                          const float* __restrict__ Wemb, const float* __restrict__ bemb,
                          const float* __restrict__ Wpro, const float* __restrict__ bpro){
    __shared__ float sPN  [NPROTO_*P_];
    __shared__ float sPNL2[NPROTO_*P_];
    __shared__ float sWe[E_*P_];
    __shared__ float sWp[E_*P_];
    __shared__ float sbe[E_];
    __shared__ float sbp[E_];
    int tid = threadIdx.x;
    if (blockIdx.x == 0 && tid < B_*H_) g_KMAX[tid] = 0.f;
    {
        float v[P_]; float s = 0.f;
        #pragma unroll
        for (int p = 0; p < P_; p++){ v[p] = proto[tid*P_ + p]; s += v[p]; }
        float m = s * (1.f/P_);
        float var = 0.f;
        #pragma unroll
        for (int p = 0; p < P_; p++){ float dd = v[p]-m; var += dd*dd; }
        var *= (1.f/P_);
        float rs = rsqrtf(var + 1e-5f);
        float nrm = 0.f;
        #pragma unroll
        for (int p = 0; p < P_; p++){ v[p] = (v[p]-m)*rs; nrm += v[p]*v[p]; sPN[tid*P_+p] = v[p]; }
        float inv = 1.f / fmaxf(sqrtf(nrm), 1e-12f);
        #pragma unroll
        for (int p = 0; p < P_; p++) sPNL2[tid*P_+p] = v[p]*inv;
    }
    for (int i = tid; i < E_*P_; i += 256){ sWe[i] = Wemb[i]; sWp[i] = Wpro[i]; }
    if (tid < E_){ sbe[tid] = bemb[tid]; sbp[tid] = bpro[tid]; }
    __syncthreads();

    int warp = tid >> 5, lane = tid & 31;
    int r = blockIdx.x*8 + warp;
    int b = r >> 9; int n = (r >> 3) & 63; int d = r & 7;
    const float* xp = x + ((b*64 + n)*6)*8 + d;

    float v[6]; float s = 0.f;
    #pragma unroll
    for (int p = 0; p < 6; p++){ v[p] = xp[p*8]; s += v[p]; }
    float mean = s * (1.f/6.f);
    float var = 0.f;
    #pragma unroll
    for (int p = 0; p < 6; p++){ float dd = v[p]-mean; var += dd*dd; }
    var *= (1.f/6.f);
    float rs = rsqrtf(var + 1e-5f);
    float xn[6];
    #pragma unroll
    for (int p = 0; p < 6; p++) xn[p] = (v[p]-mean)*rs;

    float best = -1e30f; int bi = 0;
    #pragma unroll
    for (int i = 0; i < 8; i++){
        int pidx = i*32 + lane;
        const float* pr = &sPNL2[pidx*6];
        float sim = xn[0]*pr[0] + xn[1]*pr[1] + xn[2]*pr[2]
                  + xn[3]*pr[3] + xn[4]*pr[4] + xn[5]*pr[5];
        if (sim > best){ best = sim; bi = pidx; }
    }
    #pragma unroll
    for (int off = 16; off; off >>= 1){
        float ov = __shfl_xor_sync(0xffffffffu, best, off);
        int   oi = __shfl_xor_sync(0xffffffffu, bi,   off);
        if (ov > best || (ov == best && oi < bi)){ best = ov; bi = oi; }
    }

    float sel[6];
    #pragma unroll
    for (int p = 0; p < 6; p++) sel[p] = sPN[bi*6 + p];

    #pragma unroll
    for (int e4 = 0; e4 < 4; e4++){
        int e = e4*32 + lane;
        const float* we = &sWe[e*6];
        const float* wp = &sWp[e*6];
        float a1 = sbe[e], a2 = sbp[e];
        #pragma unroll
        for (int p = 0; p < 6; p++){ a1 += xn[p]*we[p]; a2 += sel[p]*wp[p]; }
        g_IE[r*E_ + e] = a1;
        g_PE[r*E_ + e] = a2;
    }
}

// ---------------- tf32 tensor-core GEMM, fragment-major smem ------------------
// EPI: 0 = plain fp32; 1 = scaled tf32-bit store + q-norm; 2 = tf32-bit store + kmax.
template<int RELU, int CONCAT, int KK, int EPI>
__global__ void __launch_bounds__(256) k_mmagemm(int aId, const float* __restrict__ W,
                        const float* __restrict__ bias, int cId, int Nn){
    __shared__ __align__(16) unsigned sA[32*132];
    __shared__ __align__(16) unsigned sW[32*66];
    float* C = bufptr(cId);
    int t = threadIdx.x;
    int m0 = blockIdx.x * 128, n0 = blockIdx.y * 64;
    const float* Abase;
    if (CONCAT){
        int bb = m0 >> 10, j = m0 & 1023;
        Abase = ((j < 512) ? g_IE : g_PE) + (size_t)(bb*512 + (j & 511)) * KK;
    } else {
        Abase = bufptr(aId) + (size_t)m0 * KK;
    }
    int lane = t & 31, warp = t >> 5;
    int wm = warp >> 1, wn = warp & 1;
    int lq = lane >> 2, lc = lane & 3;
    int arow = t >> 3, ac4 = (t & 7)*4;
    int ksld = ac4 >> 3;
    int aslot = 2*((ac4 >> 2) & 1);
    int bslot = (ac4 >> 2) & 1;

    float c[2][4][4];
    #pragma unroll
    for (int mt = 0; mt < 2; mt++)
        #pragma unroll
        for (int nt = 0; nt < 4; nt++)
            c[mt][nt][0]=c[mt][nt][1]=c[mt][nt][2]=c[mt][nt][3]=0.f;

    float4 pa[4], pw[2];
    #pragma unroll
    for (int i = 0; i < 4; i++)
        pa[i] = *(const float4*)&Abase[(size_t)(arow + i*32)*KK + ac4];
    #pragma unroll
    for (int i = 0; i < 2; i++)
        pw[i] = *(const float4*)&W[(size_t)(n0 + arow + i*32)*KK + ac4];

    for (int k0 = 0; k0 < KK; k0 += 32){
        #pragma unroll
        for (int i = 0; i < 4; i++){
            int row = arow + i*32;
            int fa = (row >> 4)*4 + ksld;
            unsigned* d = &sA[fa*132 + (row & 7)*16 + ((row >> 3) & 1) + aslot];
            d[0]=f2tf(pa[i].x); d[4]=f2tf(pa[i].y); d[8]=f2tf(pa[i].z); d[12]=f2tf(pa[i].w);
        }
        #pragma unroll
        for (int i = 0; i < 2; i++){
            int row = arow + i*32;
            int fb = (row >> 3)*4 + ksld;
            unsigned* d = &sW[fb*66 + (row & 7)*8 + bslot];
            d[0]=f2tf(pw[i].x); d[2]=f2tf(pw[i].y); d[4]=f2tf(pw[i].z); d[6]=f2tf(pw[i].w);
        }
        __syncthreads();
        if (k0 + 32 < KK){
            #pragma unroll
            for (int i = 0; i < 4; i++)
                pa[i] = *(const float4*)&Abase[(size_t)(arow + i*32)*KK + k0 + 32 + ac4];
            #pragma unroll
            for (int i = 0; i < 2; i++)
                pw[i] = *(const float4*)&W[(size_t)(n0 + arow + i*32)*KK + k0 + 32 + ac4];
        }
        #pragma unroll
        for (int ks = 0; ks < 4; ks++){
            unsigned a[2][4], bf[4][2];
            #pragma unroll
            for (int mt = 0; mt < 2; mt++)
                *(uint4*)a[mt] = *(const uint4*)&sA[((2*wm + mt)*4 + ks)*132 + lane*4];
            #pragma unroll
            for (int nt = 0; nt < 4; nt++)
                *(uint2*)bf[nt] = *(const uint2*)&sW[((4*wn + nt)*4 + ks)*66 + lane*2];
            #pragma unroll
            for (int mt = 0; mt < 2; mt++)
                #pragma unroll
                for (int nt = 0; nt < 4; nt++)
                    mma_tf32(c[mt][nt], a[mt], bf[nt]);
        }
        __syncthreads();
    }
    #pragma unroll
    for (int nt = 0; nt < 4; nt++){
        int col = n0 + wn*32 + nt*8 + 2*lc;
        float b0 = bias[col], b1 = bias[col+1];
        #pragma unroll
        for (int mt = 0; mt < 2; mt++){
            int row = m0 + wm*32 + mt*16 + lq;
            float v0 = c[mt][nt][0] + b0, v1 = c[mt][nt][1] + b1;
            float v2 = c[mt][nt][2] + b0, v3 = c[mt][nt][3] + b1;
            if (RELU){
                v0 = fmaxf(v0,0.f); v1 = fmaxf(v1,0.f);
                v2 = fmaxf(v2,0.f); v3 = fmaxf(v3,0.f);
            }
            if (EPI == 1){ v0 *= QSCALE_; v1 *= QSCALE_; v2 *= QSCALE_; v3 *= QSCALE_; }
            if (EPI == 0){
                *(float2*)&C[(size_t)row*Nn + col]     = make_float2(v0, v1);
                *(float2*)&C[(size_t)(row+8)*Nn + col] = make_float2(v2, v3);
            } else {
                *(float2*)&C[(size_t)row*Nn + col] = make_float2(
                    __uint_as_float(f2tf(v0)), __uint_as_float(f2tf(v1)));
                *(float2*)&C[(size_t)(row+8)*Nn + col] = make_float2(
                    __uint_as_float(f2tf(v2)), __uint_as_float(f2tf(v3)));
            }
            c[mt][nt][0]=v0; c[mt][nt][1]=v1; c[mt][nt][2]=v2; c[mt][nt][3]=v3;
        }
    }
    if (EPI == 1){
        #pragma unroll
        for (int p = 0; p < 2; p++){
            int head = (n0 >> 4) + wn*2 + p;
            #pragma unroll
            for (int mt = 0; mt < 2; mt++){
                float s0 = 0.f, s1 = 0.f;
                #pragma unroll
                for (int q = 0; q < 2; q++){
                    int nt = 2*p + q;
                    s0 += c[mt][nt][0]*c[mt][nt][0] + c[mt][nt][1]*c[mt][nt][1];
                    s1 += c[mt][nt][2]*c[mt][nt][2] + c[mt][nt][3]*c[mt][nt][3];
                }
                s0 += __shfl_xor_sync(0xffffffffu, s0, 1);
                s0 += __shfl_xor_sync(0xffffffffu, s0, 2);
                s1 += __shfl_xor_sync(0xffffffffu, s1, 1);
                s1 += __shfl_xor_sync(0xffffffffu, s1, 2);
                if (lc == 0){
                    int row = m0 + wm*32 + mt*16 + lq;
                    g_QN[row*8 + head]     = sqrtf(s0);
                    g_QN[(row+8)*8 + head] = sqrtf(s1);
                }
            }
        }
    }
    if (EPI == 2 && n0 < 128){
        int bb = m0 >> 10;
        #pragma unroll
        for (int p = 0; p < 2; p++){
            int head = (n0 >> 4) + wn*2 + p;
            float mx = 0.f;
            #pragma unroll
            for (int mt = 0; mt < 2; mt++){
                float s0 = 0.f, s1 = 0.f;
                #pragma unroll
                for (int q = 0; q < 2; q++){
                    int nt = 2*p + q;
                    s0 += c[mt][nt][0]*c[mt][nt][0] + c[mt][nt][1]*c[mt][nt][1];
                    s1 += c[mt][nt][2]*c[mt][nt][2] + c[mt][nt][3]*c[mt][nt][3];
                }
                s0 += __shfl_xor_sync(0xffffffffu, s0, 1);
                s0 += __shfl_xor_sync(0xffffffffu, s0, 2);
                s1 += __shfl_xor_sync(0xffffffffu, s1, 1);
                s1 += __shfl_xor_sync(0xffffffffu, s1, 2);
                mx = fmaxf(mx, fmaxf(s0, s1));
            }
            #pragma unroll
            for (int off = 16; off; off >>= 1)
                mx = fmaxf(mx, __shfl_xor_sync(0xffffffffu, mx, off));
            if (lane == 0)
                atomicMax((unsigned*)&g_KMAX[bb*8 + head], __float_as_uint(mx));
        }
    }
}

// ---------------- attention: bound folded into accumulator, packed-h2 V -------
// grid = B*H*2; 8 warps/block; warp = 32 q rows. p = ex2(s) single MUFU.
__global__ void __launch_bounds__(256) k_attn(){
    __shared__ unsigned sK[32*20];
    __shared__ unsigned sVp[16*24];       // V key-pairs packed f16x2, stride 24
    int blk = blockIdx.x;                 // 0..255
    int bh = blk >> 1, qh = blk & 1;
    int b = bh >> 3, h = bh & 7;
    int t = threadIdx.x;
    int lane = t & 31, warp = t >> 5;
    int lq = lane >> 2, lc = lane & 3;
    int qrow0 = b*512 + qh*256 + warp*32;
    int hoff = h*16;
    const unsigned* Qb  = (const unsigned*)(g_Q  + (size_t)qrow0*E_ + hoff);
    const unsigned* KVb = (const unsigned*)(g_KVO + (size_t)(b*1024)*256);

    unsigned qa[2][2][4];
    #pragma unroll
    for (int mt = 0; mt < 2; mt++)
        #pragma unroll
        for (int ks = 0; ks < 2; ks++){
            const unsigned* qp = Qb + (size_t)(mt*16)*E_ + ks*8;
            qa[mt][ks][0] = qp[(size_t)lq*E_     + lc];
            qa[mt][ks][1] = qp[(size_t)(lq+8)*E_ + lc];
            qa[mt][ks][2] = qp[(size_t)lq*E_     + lc+4];
            qa[mt][ks][3] = qp[(size_t)(lq+8)*E_ + lc+4];
        }

    float kmax = sqrtf(g_KMAX[bh]);
    float mb2[2][2];
    #pragma unroll
    for (int mt = 0; mt < 2; mt++){
        mb2[mt][0] = g_QN[(qrow0 + mt*16 + lq  )*8 + h] * kmax;
        mb2[mt][1] = g_QN[(qrow0 + mt*16 + lq+8)*8 + h] * kmax;
    }

    float o[2][2][4];
    float lf[2][4];
    #pragma unroll
    for (int mt = 0; mt < 2; mt++){
        #pragma unroll
        for (int d = 0; d < 2; d++)
            o[mt][d][0]=o[mt][d][1]=o[mt][d][2]=o[mt][d][3]=0.f;
        lf[mt][0]=lf[mt][1]=lf[mt][2]=lf[mt][3]=0.f;
    }
    const unsigned ones[2] = {0x3C003C00u, 0x3C003C00u};

    // staging roles: t<128 stage K (32 rows x 16 cols), t>=128 stage packed V
    int krow = t >> 2, kq = (t & 3)*4;            // t<128
    int u = t - 128, vpair = u >> 3, vcp = (u & 7)*2;  // t>=128

    #pragma unroll 1
    for (int key0 = 0; key0 < 1024; key0 += 32){
        if (t < 128){
            const uint4 v = *(const uint4*)(KVb + (size_t)(key0 + krow)*256 + hoff + kq);
            *(uint4*)&sK[krow*20 + kq] = v;
        } else {
            const float* r0 = (const float*)(KVb + (size_t)(key0 + 2*vpair    )*256 + 128 + hoff + vcp);
            const float* r1 = (const float*)(KVb + (size_t)(key0 + 2*vpair + 1)*256 + 128 + hoff + vcp);
            float2 a = *(const float2*)r0;
            float2 bb = *(const float2*)r1;
            unsigned p0 = pack_h2(a.x, bb.x);
            unsigned p1 = pack_h2(a.y, bb.y);
            *(uint2*)&sVp[vpair*24 + vcp] = make_uint2(p0, p1);
        }
        __syncthreads();

        #pragma unroll
        for (int sub = 0; sub < 2; sub++){
            int r16 = sub*16;
            unsigned kb[2][2][2];
            #pragma unroll
            for (int nt = 0; nt < 2; nt++)
                #pragma unroll
                for (int ks = 0; ks < 2; ks++){
                    const unsigned* kp = &sK[(r16 + nt*8 + lq)*20 + ks*8 + lc];
                    kb[nt][ks][0] = kp[0];
                    kb[nt][ks][1] = kp[4];
                }
            // scores with bound folded into the accumulator init
            float s[2][2][4];
            #pragma unroll
            for (int mt = 0; mt < 2; mt++)
                #pragma unroll
                for (int nt = 0; nt < 2; nt++){
                    s[mt][nt][0] = -mb2[mt][0]; s[mt][nt][1] = -mb2[mt][0];
                    s[mt][nt][2] = -mb2[mt][1]; s[mt][nt][3] = -mb2[mt][1];
                    mma_tf32(s[mt][nt], qa[mt][0], kb[nt][0]);
                    mma_tf32(s[mt][nt], qa[mt][1], kb[nt][1]);
                }
            // p = 2^s, single MUFU each
            #pragma unroll
            for (int mt = 0; mt < 2; mt++)
                #pragma unroll
                for (int nt = 0; nt < 2; nt++){
                    s[mt][nt][0] = ex2(s[mt][nt][0]);
                    s[mt][nt][1] = ex2(s[mt][nt][1]);
                    s[mt][nt][2] = ex2(s[mt][nt][2]);
                    s[mt][nt][3] = ex2(s[mt][nt][3]);
                }
            // V B-frags: packed h2, direct loads
            unsigned vb[2][2];
            #pragma unroll
            for (int d = 0; d < 2; d++){
                vb[d][0] = sVp[(sub*8 + lc    )*24 + d*8 + lq];
                vb[d][1] = sVp[(sub*8 + lc + 4)*24 + d*8 + lq];
            }
            // P A-frags: direct pack of C-fragments; lsum via ones-mma
            #pragma unroll
            for (int mt = 0; mt < 2; mt++){
                unsigned pa[4];
                pa[0] = pack_h2(s[mt][0][0], s[mt][0][1]);
                pa[1] = pack_h2(s[mt][0][2], s[mt][0][3]);
                pa[2] = pack_h2(s[mt][1][0], s[mt][1][1]);
                pa[3] = pack_h2(s[mt][1][2], s[mt][1][3]);
                mma_f16(o[mt][0], pa, vb[0]);
                mma_f16(o[mt][1], pa, vb[1]);
                mma_f16(lf[mt],   pa, ones);
            }
        }
        __syncthreads();
    }

    #pragma unroll
    for (int mt = 0; mt < 2; mt++){
        float inv0 = 1.f / lf[mt][0];
        float inv1 = 1.f / lf[mt][2];
        #pragma unroll
        for (int d = 0; d < 2; d++){
            float* op = g_AT + (size_t)(qrow0 + mt*16 + lq)*E_ + hoff + d*8 + 2*lc;
            *(float2*)op = make_float2(o[mt][d][0]*inv0, o[mt][d][1]*inv0);
            *(float2*)(op + 8*E_) = make_float2(o[mt][d][2]*inv1, o[mt][d][3]*inv1);
        }
    }
}

// ---------------- residual + LayerNorm (row = 128) ----------------
__global__ void k_lnres(int aId, int rId, const float* __restrict__ g,
                        const float* __restrict__ be, int oId){
    const float* A = bufptr(aId);
    const float* R = bufptr(rId);
    float* out = bufptr(oId);
    int tid = threadIdx.x; int warp = tid >> 5, lane = tid & 31;
    int row = blockIdx.x*8 + warp;
    float v[4];
    #pragma unroll
    for (int i = 0; i < 4; i++){
        int e = i*32 + lane;
        v[i] = A[(size_t)row*E_ + e] + R[(size_t)row*E_ + e];
    }
    float s  = v[0]+v[1]+v[2]+v[3];
    float s2 = v[0]*v[0]+v[1]*v[1]+v[2]*v[2]+v[3]*v[3];
    #pragma unroll
    for (int off = 16; off; off >>= 1){
        s  += __shfl_xor_sync(0xffffffffu, s,  off);
        s2 += __shfl_xor_sync(0xffffffffu, s2, off);
    }
    float mean = s * (1.f/128.f);
    float var  = s2 * (1.f/128.f) - mean*mean;
    float rs = rsqrtf(var + 1e-5f);
    #pragma unroll
    for (int i = 0; i < 4; i++){
        int e = i*32 + lane;
        out[(size_t)row*E_ + e] = (v[i]-mean)*rs*g[e] + be[e];
    }
}

// ---------------- final projection: split-K over 65536 (fp32) -----------------
__global__ void k_splitk(const float* __restrict__ W){
    __shared__ float Zs[16*32];
    __shared__ float Ws_[32*129];
    int t = threadIdx.x;
    int kb = blockIdx.x * KCSZ_;
    int o = t & 127;
    int bset = t >> 7;
    float acc[8];
    #pragma unroll
    for (int i = 0; i < 8; i++) acc[i] = 0.f;
    for (int k0 = 0; k0 < KCSZ_; k0 += 32){
        #pragma unroll
        for (int i = 0; i < 2; i++){
            int e = t + i*256; int b_ = e >> 5, kk = e & 31;
            Zs[b_*32 + kk] = g_Z[(size_t)b_*KOUT_ + kb + k0 + kk];
        }
        #pragma unroll
        for (int i = 0; i < 16; i++){
            int e = t + i*256; int oo = e >> 5, kk = e & 31;
            Ws_[kk*129 + oo] = W[(size_t)oo*KOUT_ + kb + k0 + kk];
        }
        __syncthreads();
        #pragma unroll
        for (int kk = 0; kk < 32; kk++){
            float w = Ws_[kk*129 + o];
            #pragma unroll
            for (int i = 0; i < 8; i++)
                acc[i] += Zs[(bset*8 + i)*32 + kk] * w;
        }
        __syncthreads();
    }
    #pragma unroll
    for (int i = 0; i < 8; i++)
        g_PART[blockIdx.x*2048 + (bset*8 + i)*128 + o] = acc[i];
}

__global__ void k_reduce(const float* __restrict__ bout, float* __restrict__ out){
    int e = blockIdx.x*256 + threadIdx.x;   // 0..2047
    float s = bout[e & 127];
    #pragma unroll 8
    for (int c = 0; c < KCHUNKS_; c++) s += g_PART[c*2048 + e];
    out[e] = s;
}

// ---------------- launch ----------------
extern "C" void kernel_launch(void* const* d_in, const int* in_sizes, int n_in,
                              void* d_out, int out_size){
    const float* x    = (const float*)d_in[0];
    const float* prot = (const float*)d_in[1];
    const float* Wemb = (const float*)d_in[2];
    const float* bemb = (const float*)d_in[3];
    const float* Wpro = (const float*)d_in[4];
    const float* bpro = (const float*)d_in[5];
    const float* inw  = (const float*)d_in[6];
    const float* inb  = (const float*)d_in[7];
    const float* ow   = (const float*)d_in[8];
    const float* ob   = (const float*)d_in[9];
    const float* W1   = (const float*)d_in[10];
    const float* b1   = (const float*)d_in[11];
    const float* W2   = (const float*)d_in[12];
    const float* b2   = (const float*)d_in[13];
    const float* g1   = (const float*)d_in[14];
    const float* be1  = (const float*)d_in[15];
    const float* g2   = (const float*)d_in[16];
    const float* be2  = (const float*)d_in[17];
    const float* Wout = (const float*)d_in[18];
    const float* bout = (const float*)d_in[19];
    float* out = (float*)d_out;

    k_rowprep<<<1024, 256>>>(x, prot, Wemb, bemb, Wpro, bpro);
    k_mmagemm<0,0,128,1><<<dim3(TOK_/128, 2), 256>>>(0, inw, inb, 2, 128);
    k_mmagemm<0,1,128,2><<<dim3(KVN_/128, 4), 256>>>(0, inw + 128*E_, inb + 128, 3, 256);
    k_attn<<<B_*H_*2, 256>>>();
    k_mmagemm<0,0,128,0><<<dim3(TOK_/128, 2), 256>>>(4, ow, ob, 5, 128);
    k_lnres<<<TOK_/8, 256>>>(0, 5, g1, be1, 6);
    k_mmagemm<1,0,128,0><<<dim3(TOK_/128, 1), 256>>>(6, W1, b1, 7, 64);
    k_mmagemm<0,0,64,0><<<dim3(TOK_/128, 2), 256>>>(7, W2, b2, 8, 128);
    k_lnres<<<TOK_/8, 256>>>(6, 8, g2, be2, 9);
    k_splitk<<<KCHUNKS_, 256>>>(Wout);
    k_reduce<<<8, 256>>>(bout, out);
}

// round 17
// speedup vs baseline: 1.2444x; 1.0471x over previous
#include <cuda_runtime.h>

// ---------------- problem constants ----------------
#define B_      16
#define N_      64
#define P_      6
#define D_      8
#define E_      128
#define H_      8
#define HD_     16
#define S_      512            // N*D tokens per batch
#define TOK_    (B_*S_)        // 8192
#define KVN_    (B_*2*S_)      // 16384
#define NPROTO_ 256            // D * 32 prototype rows
#define I_      64
#define O_      128
#define KOUT_   (S_*E_)        // 65536
#define KCHUNKS_ 256
#define KCSZ_   (KOUT_/KCHUNKS_) // 256
#define QSCALE_ (0.25f*1.4426950408889634f)   // fold 1/sqrt(Hd) and log2e into Q

// ---------------- device scratch (no allocations allowed) ----------------
__device__ float g_IE  [TOK_*E_];
__device__ float g_PE  [TOK_*E_];
__device__ float g_Q   [TOK_*E_];     // tf32 bits of q*QSCALE (attention-only)
__device__ float g_KVO [KVN_*2*E_];   // tf32 bits; cols 0..127 K, 128..255 V
__device__ float g_AT  [TOK_*E_];
__device__ float g_AP  [TOK_*E_];
__device__ float g_H1  [TOK_*E_];
__device__ float g_F1  [TOK_*I_];
__device__ float g_F2  [TOK_*E_];
__device__ float g_Z   [TOK_*E_];
__device__ float g_PART[KCHUNKS_*B_*O_];
__device__ float g_QN  [TOK_*H_];     // per (qrow, head) L2 norm of SCALED q
__device__ float g_KMAX[B_*H_];       // per (b, head) max key norm^2 (bits, atomicMax)

__device__ __forceinline__ float* bufptr(int id){
    switch(id){
        case 0: return g_IE;
        case 2: return g_Q;
        case 3: return g_KVO;
        case 4: return g_AT;
        case 5: return g_AP;
        case 6: return g_H1;
        case 7: return g_F1;
        case 8: return g_F2;
        default: return g_Z;
    }
}

// ---------------- mma helpers ----------------
__device__ __forceinline__ unsigned f2tf(float f){
    unsigned r; asm("cvt.rna.tf32.f32 %0, %1;" : "=r"(r) : "f"(f)); return r;
}
__device__ __forceinline__ unsigned pack_h2(float lo, float hi){
    unsigned r; asm("cvt.rn.f16x2.f32 %0, %1, %2;" : "=r"(r) : "f"(hi), "f"(lo)); return r;
}
__device__ __forceinline__ float ex2(float x){
    float r; asm("ex2.approx.f32 %0, %1;" : "=f"(r) : "f"(x)); return r;
}
__device__ __forceinline__ void mma_tf32(float c[4], const unsigned a[4], const unsigned b[2]){
    asm volatile("mma.sync.aligned.m16n8k8.row.col.f32.tf32.tf32.f32 "
        "{%0,%1,%2,%3}, {%4,%5,%6,%7}, {%8,%9}, {%0,%1,%2,%3};"
        : "+f"(c[0]), "+f"(c[1]), "+f"(c[2]), "+f"(c[3])
        : "r"(a[0]), "r"(a[1]), "r"(a[2]), "r"(a[3]), "r"(b[0]), "r"(b[1]));
}
__device__ __forceinline__ void mma_f16(float c[4], const unsigned a[4], const unsigned b[2]){
    asm volatile("mma.sync.aligned.m16n8k16.row.col.f32.f16.f16.f32 "
        "{%0,%1,%2,%3}, {%4,%5,%6,%7}, {%8,%9}, {%0,%1,%2,%3};"
        : "+f"(c[0]), "+f"(c[1]), "+f"(c[2]), "+f"(c[3])
        : "r"(a[0]), "r"(a[1]), "r"(a[2]), "r"(a[3]), "r"(b[0]), "r"(b[1]));
}

// ---------------- rowprep: proto inorm (in-block) + x inorm + argmax + embeds ----
__global__ void k_rowprep(const float* __restrict__ x, const float* __restrict__ proto,
                          const float* __restrict__ Wemb, const float* __restrict__ bemb,
                          const float* __restrict__ Wpro, const float* __restrict__ bpro){
    __shared__ float sPN  [NPROTO_*P_];
    __shared__ float sPNL2[NPROTO_*P_];
    __shared__ float sWe[E_*P_];
    __shared__ float sWp[E_*P_];
    __shared__ float sbe[E_];
    __shared__ float sbp[E_];
    int tid = threadIdx.x;
    if (blockIdx.x == 0 && tid < B_*H_) g_KMAX[tid] = 0.f;
    {
        float v[P_]; float s = 0.f;
        #pragma unroll
        for (int p = 0; p < P_; p++){ v[p] = proto[tid*P_ + p]; s += v[p]; }
        float m = s * (1.f/P_);
        float var = 0.f;
        #pragma unroll
        for (int p = 0; p < P_; p++){ float dd = v[p]-m; var += dd*dd; }
        var *= (1.f/P_);
        float rs = rsqrtf(var + 1e-5f);
        float nrm = 0.f;
        #pragma unroll
        for (int p = 0; p < P_; p++){ v[p] = (v[p]-m)*rs; nrm += v[p]*v[p]; sPN[tid*P_+p] = v[p]; }
        float inv = 1.f / fmaxf(sqrtf(nrm), 1e-12f);
        #pragma unroll
        for (int p = 0; p < P_; p++) sPNL2[tid*P_+p] = v[p]*inv;
    }
    for (int i = tid; i < E_*P_; i += 256){ sWe[i] = Wemb[i]; sWp[i] = Wpro[i]; }
    if (tid < E_){ sbe[tid] = bemb[tid]; sbp[tid] = bpro[tid]; }
    __syncthreads();

    int warp = tid >> 5, lane = tid & 31;
    int r = blockIdx.x*8 + warp;
    int b = r >> 9; int n = (r >> 3) & 63; int d = r & 7;
    const float* xp = x + ((b*64 + n)*6)*8 + d;

    float v[6]; float s = 0.f;
    #pragma unroll
    for (int p = 0; p < 6; p++){ v[p] = xp[p*8]; s += v[p]; }
    float mean = s * (1.f/6.f);
    float var = 0.f;
    #pragma unroll
    for (int p = 0; p < 6; p++){ float dd = v[p]-mean; var += dd*dd; }
    var *= (1.f/6.f);
    float rs = rsqrtf(var + 1e-5f);
    float xn[6];
    #pragma unroll
    for (int p = 0; p < 6; p++) xn[p] = (v[p]-mean)*rs;

    float best = -1e30f; int bi = 0;
    #pragma unroll
    for (int i = 0; i < 8; i++){
        int pidx = i*32 + lane;
        const float* pr = &sPNL2[pidx*6];
        float sim = xn[0]*pr[0] + xn[1]*pr[1] + xn[2]*pr[2]
                  + xn[3]*pr[3] + xn[4]*pr[4] + xn[5]*pr[5];
        if (sim > best){ best = sim; bi = pidx; }
    }
    #pragma unroll
    for (int off = 16; off; off >>= 1){
        float ov = __shfl_xor_sync(0xffffffffu, best, off);
        int   oi = __shfl_xor_sync(0xffffffffu, bi,   off);
        if (ov > best || (ov == best && oi < bi)){ best = ov; bi = oi; }
    }

    float sel[6];
    #pragma unroll
    for (int p = 0; p < 6; p++) sel[p] = sPN[bi*6 + p];

    #pragma unroll
    for (int e4 = 0; e4 < 4; e4++){
        int e = e4*32 + lane;
        const float* we = &sWe[e*6];
        const float* wp = &sWp[e*6];
        float a1 = sbe[e], a2 = sbp[e];
        #pragma unroll
        for (int p = 0; p < 6; p++){ a1 += xn[p]*we[p]; a2 += sel[p]*wp[p]; }
        g_IE[r*E_ + e] = a1;
        g_PE[r*E_ + e] = a2;
    }
}

// ---------------- tf32 tensor-core GEMM, fragment-major smem ------------------
// EPI: 0 = plain fp32; 1 = scaled tf32-bit store + q-norm; 2 = tf32-bit store + kmax.
template<int RELU, int CONCAT, int KK, int EPI>
__global__ void __launch_bounds__(256) k_mmagemm(int aId, const float* __restrict__ W,
                        const float* __restrict__ bias, int cId, int Nn){
    __shared__ __align__(16) unsigned sA[32*132];
    __shared__ __align__(16) unsigned sW[32*66];
    float* C = bufptr(cId);
    int t = threadIdx.x;
    int m0 = blockIdx.x * 128, n0 = blockIdx.y * 64;
    const float* Abase;
    if (CONCAT){
        int bb = m0 >> 10, j = m0 & 1023;
        Abase = ((j < 512) ? g_IE : g_PE) + (size_t)(bb*512 + (j & 511)) * KK;
    } else {
        Abase = bufptr(aId) + (size_t)m0 * KK;
    }
    int lane = t & 31, warp = t >> 5;
    int wm = warp >> 1, wn = warp & 1;
    int lq = lane >> 2, lc = lane & 3;
    int arow = t >> 3, ac4 = (t & 7)*4;
    int ksld = ac4 >> 3;
    int aslot = 2*((ac4 >> 2) & 1);
    int bslot = (ac4 >> 2) & 1;

    float c[2][4][4];
    #pragma unroll
    for (int mt = 0; mt < 2; mt++)
        #pragma unroll
        for (int nt = 0; nt < 4; nt++)
            c[mt][nt][0]=c[mt][nt][1]=c[mt][nt][2]=c[mt][nt][3]=0.f;

    float4 pa[4], pw[2];
    #pragma unroll
    for (int i = 0; i < 4; i++)
        pa[i] = *(const float4*)&Abase[(size_t)(arow + i*32)*KK + ac4];
    #pragma unroll
    for (int i = 0; i < 2; i++)
        pw[i] = *(const float4*)&W[(size_t)(n0 + arow + i*32)*KK + ac4];

    for (int k0 = 0; k0 < KK; k0 += 32){
        #pragma unroll
        for (int i = 0; i < 4; i++){
            int row = arow + i*32;
            int fa = (row >> 4)*4 + ksld;
            unsigned* d = &sA[fa*132 + (row & 7)*16 + ((row >> 3) & 1) + aslot];
            d[0]=f2tf(pa[i].x); d[4]=f2tf(pa[i].y); d[8]=f2tf(pa[i].z); d[12]=f2tf(pa[i].w);
        }
        #pragma unroll
        for (int i = 0; i < 2; i++){
            int row = arow + i*32;
            int fb = (row >> 3)*4 + ksld;
            unsigned* d = &sW[fb*66 + (row & 7)*8 + bslot];
            d[0]=f2tf(pw[i].x); d[2]=f2tf(pw[i].y); d[4]=f2tf(pw[i].z); d[6]=f2tf(pw[i].w);
        }
        __syncthreads();
        if (k0 + 32 < KK){
            #pragma unroll
            for (int i = 0; i < 4; i++)
                pa[i] = *(const float4*)&Abase[(size_t)(arow + i*32)*KK + k0 + 32 + ac4];
            #pragma unroll
            for (int i = 0; i < 2; i++)
                pw[i] = *(const float4*)&W[(size_t)(n0 + arow + i*32)*KK + k0 + 32 + ac4];
        }
        #pragma unroll
        for (int ks = 0; ks < 4; ks++){
            unsigned a[2][4], bf[4][2];
            #pragma unroll
            for (int mt = 0; mt < 2; mt++)
                *(uint4*)a[mt] = *(const uint4*)&sA[((2*wm + mt)*4 + ks)*132 + lane*4];
            #pragma unroll
            for (int nt = 0; nt < 4; nt++)
                *(uint2*)bf[nt] = *(const uint2*)&sW[((4*wn + nt)*4 + ks)*66 + lane*2];
            #pragma unroll
            for (int mt = 0; mt < 2; mt++)
                #pragma unroll
                for (int nt = 0; nt < 4; nt++)
                    mma_tf32(c[mt][nt], a[mt], bf[nt]);
        }
        __syncthreads();
    }
    #pragma unroll
    for (int nt = 0; nt < 4; nt++){
        int col = n0 + wn*32 + nt*8 + 2*lc;
        float b0 = bias[col], b1 = bias[col+1];
        #pragma unroll
        for (int mt = 0; mt < 2; mt++){
            int row = m0 + wm*32 + mt*16 + lq;
            float v0 = c[mt][nt][0] + b0, v1 = c[mt][nt][1] + b1;
            float v2 = c[mt][nt][2] + b0, v3 = c[mt][nt][3] + b1;
            if (RELU){
                v0 = fmaxf(v0,0.f); v1 = fmaxf(v1,0.f);
                v2 = fmaxf(v2,0.f); v3 = fmaxf(v3,0.f);
            }
            if (EPI == 1){ v0 *= QSCALE_; v1 *= QSCALE_; v2 *= QSCALE_; v3 *= QSCALE_; }
            if (EPI == 0){
                *(float2*)&C[(size_t)row*Nn + col]     = make_float2(v0, v1);
                *(float2*)&C[(size_t)(row+8)*Nn + col] = make_float2(v2, v3);
            } else {
                *(float2*)&C[(size_t)row*Nn + col] = make_float2(
                    __uint_as_float(f2tf(v0)), __uint_as_float(f2tf(v1)));
                *(float2*)&C[(size_t)(row+8)*Nn + col] = make_float2(
                    __uint_as_float(f2tf(v2)), __uint_as_float(f2tf(v3)));
            }
            c[mt][nt][0]=v0; c[mt][nt][1]=v1; c[mt][nt][2]=v2; c[mt][nt][3]=v3;
        }
    }
    if (EPI == 1){
        #pragma unroll
        for (int p = 0; p < 2; p++){
            int head = (n0 >> 4) + wn*2 + p;
            #pragma unroll
            for (int mt = 0; mt < 2; mt++){
                float s0 = 0.f, s1 = 0.f;
                #pragma unroll
                for (int q = 0; q < 2; q++){
                    int nt = 2*p + q;
                    s0 += c[mt][nt][0]*c[mt][nt][0] + c[mt][nt][1]*c[mt][nt][1];
                    s1 += c[mt][nt][2]*c[mt][nt][2] + c[mt][nt][3]*c[mt][nt][3];
                }
                s0 += __shfl_xor_sync(0xffffffffu, s0, 1);
                s0 += __shfl_xor_sync(0xffffffffu, s0, 2);
                s1 += __shfl_xor_sync(0xffffffffu, s1, 1);
                s1 += __shfl_xor_sync(0xffffffffu, s1, 2);
                if (lc == 0){
                    int row = m0 + wm*32 + mt*16 + lq;
                    g_QN[row*8 + head]     = sqrtf(s0);
                    g_QN[(row+8)*8 + head] = sqrtf(s1);
                }
            }
        }
    }
    if (EPI == 2 && n0 < 128){
        int bb = m0 >> 10;
        #pragma unroll
        for (int p = 0; p < 2; p++){
            int head = (n0 >> 4) + wn*2 + p;
            float mx = 0.f;
            #pragma unroll
            for (int mt = 0; mt < 2; mt++){
                float s0 = 0.f, s1 = 0.f;
                #pragma unroll
                for (int q = 0; q < 2; q++){
                    int nt = 2*p + q;
                    s0 += c[mt][nt][0]*c[mt][nt][0] + c[mt][nt][1]*c[mt][nt][1];
                    s1 += c[mt][nt][2]*c[mt][nt][2] + c[mt][nt][3]*c[mt][nt][3];
                }
                s0 += __shfl_xor_sync(0xffffffffu, s0, 1);
                s0 += __shfl_xor_sync(0xffffffffu, s0, 2);
                s1 += __shfl_xor_sync(0xffffffffu, s1, 1);
                s1 += __shfl_xor_sync(0xffffffffu, s1, 2);
                mx = fmaxf(mx, fmaxf(s0, s1));
            }
            #pragma unroll
            for (int off = 16; off; off >>= 1)
                mx = fmaxf(mx, __shfl_xor_sync(0xffffffffu, mx, off));
            if (lane == 0)
                atomicMax((unsigned*)&g_KMAX[bb*8 + head], __float_as_uint(mx));
        }
    }
}

// ---------------- attention: double-buffered KV staging -----------------------
// grid = B*H*2; 8 warps/block; warp = 32 q rows. p = ex2(s) single MUFU.
// Ping-pong smem: next tile's gmem loads issue before computing current tile.
__global__ void __launch_bounds__(256) k_attn(){
    __shared__ unsigned sK [2][32*20];
    __shared__ unsigned sVp[2][16*24];    // V key-pairs packed f16x2, stride 24
    int blk = blockIdx.x;                 // 0..255
    int bh = blk >> 1, qh = blk & 1;
    int b = bh >> 3, h = bh & 7;
    int t = threadIdx.x;
    int lane = t & 31, warp = t >> 5;
    int lq = lane >> 2, lc = lane & 3;
    int qrow0 = b*512 + qh*256 + warp*32;
    int hoff = h*16;
    const unsigned* Qb  = (const unsigned*)(g_Q  + (size_t)qrow0*E_ + hoff);
    const unsigned* KVb = (const unsigned*)(g_KVO + (size_t)(b*1024)*256);

    unsigned qa[2][2][4];
    #pragma unroll
    for (int mt = 0; mt < 2; mt++)
        #pragma unroll
        for (int ks = 0; ks < 2; ks++){
            const unsigned* qp = Qb + (size_t)(mt*16)*E_ + ks*8;
            qa[mt][ks][0] = qp[(size_t)lq*E_     + lc];
            qa[mt][ks][1] = qp[(size_t)(lq+8)*E_ + lc];
            qa[mt][ks][2] = qp[(size_t)lq*E_     + lc+4];
            qa[mt][ks][3] = qp[(size_t)(lq+8)*E_ + lc+4];
        }

    float kmax = sqrtf(g_KMAX[bh]);
    float mb2[2][2];
    #pragma unroll
    for (int mt = 0; mt < 2; mt++){
        mb2[mt][0] = g_QN[(qrow0 + mt*16 + lq  )*8 + h] * kmax;
        mb2[mt][1] = g_QN[(qrow0 + mt*16 + lq+8)*8 + h] * kmax;
    }

    float o[2][2][4];
    float lf[2][4];
    #pragma unroll
    for (int mt = 0; mt < 2; mt++){
        #pragma unroll
        for (int d = 0; d < 2; d++)
            o[mt][d][0]=o[mt][d][1]=o[mt][d][2]=o[mt][d][3]=0.f;
        lf[mt][0]=lf[mt][1]=lf[mt][2]=lf[mt][3]=0.f;
    }
    const unsigned ones[2] = {0x3C003C00u, 0x3C003C00u};

    // staging roles: t<128 stage K (32 rows x 16 cols), t>=128 stage packed V
    int krow = t >> 2, kq = (t & 3)*4;                 // t<128
    int u = t - 128, vpair = u >> 3, vcp = (u & 7)*2;  // t>=128

    // prologue: stage tile 0 into buffer 0
    if (t < 128){
        uint4 v = *(const uint4*)(KVb + (size_t)krow*256 + hoff + kq);
        *(uint4*)&sK[0][krow*20 + kq] = v;
    } else {
        float2 a = *(const float2*)(KVb + (size_t)(2*vpair    )*256 + 128 + hoff + vcp);
        float2 bb = *(const float2*)(KVb + (size_t)(2*vpair + 1)*256 + 128 + hoff + vcp);
        *(uint2*)&sVp[0][vpair*24 + vcp] = make_uint2(pack_h2(a.x, bb.x), pack_h2(a.y, bb.y));
    }
    __syncthreads();

    #pragma unroll 1
    for (int key0 = 0; key0 < 1024; key0 += 32){
        int cur = (key0 >> 5) & 1;
        bool more = (key0 + 32) < 1024;
        // issue next tile's gmem loads early (overlap with compute below)
        uint4 kr; float2 va, vb2;
        if (more){
            int nk = key0 + 32;
            if (t < 128){
                kr = *(const uint4*)(KVb + (size_t)(nk + krow)*256 + hoff + kq);
            } else {
                va  = *(const float2*)(KVb + (size_t)(nk + 2*vpair    )*256 + 128 + hoff + vcp);
                vb2 = *(const float2*)(KVb + (size_t)(nk + 2*vpair + 1)*256 + 128 + hoff + vcp);
            }
        }

        const unsigned* sKc  = sK[cur];
        const unsigned* sVpc = sVp[cur];
        #pragma unroll
        for (int sub = 0; sub < 2; sub++){
            int r16 = sub*16;
            unsigned kb[2][2][2];
            #pragma unroll
            for (int nt = 0; nt < 2; nt++)
                #pragma unroll
                for (int ks = 0; ks < 2; ks++){
                    const unsigned* kp = &sKc[(r16 + nt*8 + lq)*20 + ks*8 + lc];
                    kb[nt][ks][0] = kp[0];
                    kb[nt][ks][1] = kp[4];
                }
            // scores with bound folded into the accumulator init
            float s[2][2][4];
            #pragma unroll
            for (int mt = 0; mt < 2; mt++)
                #pragma unroll
                for (int nt = 0; nt < 2; nt++){
                    s[mt][nt][0] = -mb2[mt][0]; s[mt][nt][1] = -mb2[mt][0];
                    s[mt][nt][2] = -mb2[mt][1]; s[mt][nt][3] = -mb2[mt][1];
                    mma_tf32(s[mt][nt], qa[mt][0], kb[nt][0]);
                    mma_tf32(s[mt][nt], qa[mt][1], kb[nt][1]);
                }
            // p = 2^s, single MUFU each
            #pragma unroll
            for (int mt = 0; mt < 2; mt++)
                #pragma unroll
                for (int nt = 0; nt < 2; nt++){
                    s[mt][nt][0] = ex2(s[mt][nt][0]);
                    s[mt][nt][1] = ex2(s[mt][nt][1]);
                    s[mt][nt][2] = ex2(s[mt][nt][2]);
                    s[mt][nt][3] = ex2(s[mt][nt][3]);
                }
            // V B-frags: packed h2, direct loads
            unsigned vb[2][2];
            #pragma unroll
            for (int d = 0; d < 2; d++){
                vb[d][0] = sVpc[(sub*8 + lc    )*24 + d*8 + lq];
                vb[d][1] = sVpc[(sub*8 + lc + 4)*24 + d*8 + lq];
            }
            // P A-frags: direct pack of C-fragments; lsum via ones-mma
            #pragma unroll
            for (int mt = 0; mt < 2; mt++){
                unsigned pa[4];
                pa[0] = pack_h2(s[mt][0][0], s[mt][0][1]);
                pa[1] = pack_h2(s[mt][0][2], s[mt][0][3]);
                pa[2] = pack_h2(s[mt][1][0], s[mt][1][1]);
                pa[3] = pack_h2(s[mt][1][2], s[mt][1][3]);
                mma_f16(o[mt][0], pa, vb[0]);
                mma_f16(o[mt][1], pa, vb[1]);
                mma_f16(lf[mt],   pa, ones);
            }
        }
        // store next tile into the other buffer, then one sync
        if (more){
            int nxt = cur ^ 1;
            if (t < 128){
                *(uint4*)&sK[nxt][krow*20 + kq] = kr;
            } else {
                *(uint2*)&sVp[nxt][vpair*24 + vcp] =
                    make_uint2(pack_h2(va.x, vb2.x), pack_h2(va.y, vb2.y));
            }
        }
        __syncthreads();
    }

    #pragma unroll
    for (int mt = 0; mt < 2; mt++){
        float inv0 = 1.f / lf[mt][0];
        float inv1 = 1.f / lf[mt][2];
        #pragma unroll
        for (int d = 0; d < 2; d++){
            float* op = g_AT + (size_t)(qrow0 + mt*16 + lq)*E_ + hoff + d*8 + 2*lc;
            *(float2*)op = make_float2(o[mt][d][0]*inv0, o[mt][d][1]*inv0);
            *(float2*)(op + 8*E_) = make_float2(o[mt][d][2]*inv1, o[mt][d][3]*inv1);
        }
    }
}

// ---------------- residual + LayerNorm (row = 128) ----------------
__global__ void k_lnres(int aId, int rId, const float* __restrict__ g,
                        const float* __restrict__ be, int oId){
    const float* A = bufptr(aId);
    const float* R = bufptr(rId);
    float* out = bufptr(oId);
    int tid = threadIdx.x; int warp = tid >> 5, lane = tid & 31;
    int row = blockIdx.x*8 + warp;
    float v[4];
    #pragma unroll
    for (int i = 0; i < 4; i++){
        int e = i*32 + lane;
        v[i] = A[(size_t)row*E_ + e] + R[(size_t)row*E_ + e];
    }
    float s  = v[0]+v[1]+v[2]+v[3];
    float s2 = v[0]*v[0]+v[1]*v[1]+v[2]*v[2]+v[3]*v[3];
    #pragma unroll
    for (int off = 16; off; off >>= 1){
        s  += __shfl_xor_sync(0xffffffffu, s,  off);
        s2 += __shfl_xor_sync(0xffffffffu, s2, off);
    }
    float mean = s * (1.f/128.f);
    float var  = s2 * (1.f/128.f) - mean*mean;
    float rs = rsqrtf(var + 1e-5f);
    #pragma unroll
    for (int i = 0; i < 4; i++){
        int e = i*32 + lane;
        out[(size_t)row*E_ + e] = (v[i]-mean)*rs*g[e] + be[e];
    }
}

// ---------------- final projection: split-K over 65536 (fp32) -----------------
__global__ void k_splitk(const float* __restrict__ W){
    __shared__ float Zs[16*32];
    __shared__ float Ws_[32*129];
    int t = threadIdx.x;
    int kb = blockIdx.x * KCSZ_;
    int o = t & 127;
    int bset = t >> 7;
    float acc[8];
    #pragma unroll
    for (int i = 0; i < 8; i++) acc[i] = 0.f;
    for (int k0 = 0; k0 < KCSZ_; k0 += 32){
        #pragma unroll
        for (int i = 0; i < 2; i++){
            int e = t + i*256; int b_ = e >> 5, kk = e & 31;
            Zs[b_*32 + kk] = g_Z[(size_t)b_*KOUT_ + kb + k0 + kk];
        }
        #pragma unroll
        for (int i = 0; i < 16; i++){
            int e = t + i*256; int oo = e >> 5, kk = e & 31;
            Ws_[kk*129 + oo] = W[(size_t)oo*KOUT_ + kb + k0 + kk];
        }
        __syncthreads();
        #pragma unroll
        for (int kk = 0; kk < 32; kk++){
            float w = Ws_[kk*129 + o];
            #pragma unroll
            for (int i = 0; i < 8; i++)
                acc[i] += Zs[(bset*8 + i)*32 + kk] * w;
        }
        __syncthreads();
    }
    #pragma unroll
    for (int i = 0; i < 8; i++)
        g_PART[blockIdx.x*2048 + (bset*8 + i)*128 + o] = acc[i];
}

__global__ void k_reduce(const float* __restrict__ bout, float* __restrict__ out){
    int e = blockIdx.x*256 + threadIdx.x;   // 0..2047
    float s = bout[e & 127];
    #pragma unroll 8
    for (int c = 0; c < KCHUNKS_; c++) s += g_PART[c*2048 + e];
    out[e] = s;
}

// ---------------- launch ----------------
extern "C" void kernel_launch(void* const* d_in, const int* in_sizes, int n_in,
                              void* d_out, int out_size){
    const float* x    = (const float*)d_in[0];
    const float* prot = (const float*)d_in[1];
    const float* Wemb = (const float*)d_in[2];
    const float* bemb = (const float*)d_in[3];
    const float* Wpro = (const float*)d_in[4];
    const float* bpro = (const float*)d_in[5];
    const float* inw  = (const float*)d_in[6];
    const float* inb  = (const float*)d_in[7];
    const float* ow   = (const float*)d_in[8];
    const float* ob   = (const float*)d_in[9];
    const float* W1   = (const float*)d_in[10];
    const float* b1   = (const float*)d_in[11];
    const float* W2   = (const float*)d_in[12];
    const float* b2   = (const float*)d_in[13];
    const float* g1   = (const float*)d_in[14];
    const float* be1  = (const float*)d_in[15];
    const float* g2   = (const float*)d_in[16];
    const float* be2  = (const float*)d_in[17];
    const float* Wout = (const float*)d_in[18];
    const float* bout = (const float*)d_in[19];
    float* out = (float*)d_out;

    k_rowprep<<<1024, 256>>>(x, prot, Wemb, bemb, Wpro, bpro);
    k_mmagemm<0,0,128,1><<<dim3(TOK_/128, 2), 256>>>(0, inw, inb, 2, 128);
    k_mmagemm<0,1,128,2><<<dim3(KVN_/128, 4), 256>>>(0, inw + 128*E_, inb + 128, 3, 256);
    k_attn<<<B_*H_*2, 256>>>();
    k_mmagemm<0,0,128,0><<<dim3(TOK_/128, 2), 256>>>(4, ow, ob, 5, 128);
    k_lnres<<<TOK_/8, 256>>>(0, 5, g1, be1, 6);
    k_mmagemm<1,0,128,0><<<dim3(TOK_/128, 1), 256>>>(6, W1, b1, 7, 64);
    k_mmagemm<0,0,64,0><<<dim3(TOK_/128, 2), 256>>>(7, W2, b2, 8, 128);
    k_lnres<<<TOK_/8, 256>>>(6, 8, g2, be2, 9);
    k_splitk<<<KCHUNKS_, 256>>>(Wout);
    k_reduce<<<8, 256>>>(bout, out);
}